// round 13
// baseline (speedup 1.0000x reference)
#include <cuda_runtime.h>
#include <cuda_bf16.h>
#include <cstdint>

#define DH 256
#define NMAX 50000
#define EMAX 800000
#define NQMAX 12500
#define EQMAX 200000
#define GNUM 64
#define BN_EPS 1e-5f

// ---------------- scratch (static device memory) ----------------
__device__ __align__(16) float g_H [NMAX * DH];
__device__ __align__(16) float g_T1[NMAX * DH];
__device__ __align__(16) float g_T2[NMAX * DH];
__device__ __align__(16) __nv_bfloat16 g_A2[2 * NMAX * DH];   // [hi | lo] merged
__device__ int   g_deg[NMAX + 1];
__device__ int   g_rowptr[NMAX + 1];
__device__ int   g_cursor[NMAX];
__device__ int   g_eidx[EMAX];
__device__ __align__(16) float g_part[256 * 512];
__device__ __align__(16) float g_ac[3 * 512];
__device__ int   g_gstart[GNUM + 1];
__device__ __align__(16) float q_H [NQMAX * DH];
__device__ __align__(16) float q_T1[NQMAX * DH];
__device__ __align__(16) float q_T2[NQMAX * DH];
__device__ __align__(16) __nv_bfloat16 q_A2[2 * NQMAX * DH];  // [hi | lo] merged
__device__ int   q_deg[NQMAX + 1];
__device__ int   q_rowptr[NQMAX + 1];
__device__ int   q_cursor[NQMAX];
__device__ int   q_eidx[EQMAX];
__device__ __align__(16) float q_part[256 * 512];
__device__ __align__(16) float q_ac[3 * 512];
__device__ int   q_gstart[GNUM + 1];
__device__ __align__(16) float g_R[2 * GNUM * DH];

#define W_EMB_OFF 0
#define W1_OFF(l) (32768 + (l) * 65536)
#define W2_OFF(l) (32768 + 262144 + (l) * 65536)
#define WTOT      (32768 + 524288)
__device__ __align__(16) __nv_bfloat16 g_W2[2 * WTOT];        // [hi | lo] merged

#define A_LO_B_G (NMAX * DH * 2)
#define A_LO_B_Q (NQMAX * DH * 2)
#define W_LO_B   (WTOT * 2)

// ---------------- helpers ----------------
__device__ __forceinline__ uint32_t smem_u32(const void* p) {
    return (uint32_t)__cvta_generic_to_shared(p);
}
__device__ __forceinline__ void cp16(uint32_t dst, const void* src) {
    asm volatile("cp.async.cg.shared.global [%0], [%1], 16;" :: "r"(dst), "l"(src) : "memory");
}
#define CP_COMMIT() asm volatile("cp.async.commit_group;" ::: "memory")
#define CP_WAIT1()  asm volatile("cp.async.wait_group 1;" ::: "memory")
#define CP_WAIT0()  asm volatile("cp.async.wait_group 0;" ::: "memory")

__device__ __forceinline__ void mma16816(float* d, const uint32_t* a, uint32_t b0, uint32_t b1) {
    asm volatile(
        "mma.sync.aligned.m16n8k16.row.col.f32.bf16.bf16.f32 "
        "{%0,%1,%2,%3}, {%4,%5,%6,%7}, {%8,%9}, {%0,%1,%2,%3};"
        : "+f"(d[0]), "+f"(d[1]), "+f"(d[2]), "+f"(d[3])
        : "r"(a[0]), "r"(a[1]), "r"(a[2]), "r"(a[3]), "r"(b0), "r"(b1));
}
__device__ __forceinline__ void ldsm4(uint32_t& r0, uint32_t& r1, uint32_t& r2, uint32_t& r3,
                                      uint32_t addr) {
    asm volatile("ldmatrix.sync.aligned.m8n8.x4.shared.b16 {%0,%1,%2,%3}, [%4];"
                 : "=r"(r0), "=r"(r1), "=r"(r2), "=r"(r3) : "r"(addr));
}

// 64B-pitch conflict-free tile swizzle (verified R10/R11)
__device__ __forceinline__ uint32_t swz(uint32_t r, uint32_t q) {
    return (r >> 1) * 128 + (((r & 1) * 4 + (q ^ ((r >> 1) & 3))) << 4);
}

__device__ __forceinline__ uint2 split4(float4 v) {
    __nv_bfloat16 hx = __float2bfloat16(v.x), hy = __float2bfloat16(v.y);
    __nv_bfloat16 hz = __float2bfloat16(v.z), hw = __float2bfloat16(v.w);
    __nv_bfloat162 p0 = __halves2bfloat162(hx, hy);
    __nv_bfloat162 p1 = __halves2bfloat162(hz, hw);
    return make_uint2(*(uint32_t*)&p0, *(uint32_t*)&p1);
}
__device__ __forceinline__ uint2 split4lo(float4 v, uint2 hi) {
    __nv_bfloat162 h0 = *(__nv_bfloat162*)&hi.x;
    __nv_bfloat162 h1 = *(__nv_bfloat162*)&hi.y;
    __nv_bfloat16 lx = __float2bfloat16(v.x - __bfloat162float(__low2bfloat16(h0)));
    __nv_bfloat16 ly = __float2bfloat16(v.y - __bfloat162float(__high2bfloat16(h0)));
    __nv_bfloat16 lz = __float2bfloat16(v.z - __bfloat162float(__low2bfloat16(h1)));
    __nv_bfloat16 lw = __float2bfloat16(v.w - __bfloat162float(__high2bfloat16(h1)));
    __nv_bfloat162 p0 = __halves2bfloat162(lx, ly);
    __nv_bfloat162 p1 = __halves2bfloat162(lz, lw);
    return make_uint2(*(uint32_t*)&p0, *(uint32_t*)&p1);
}

// ---------------- small utility kernels ----------------
__global__ __launch_bounds__(256) void zero_int_k(int* p, int n) {
    int i = blockIdx.x * 256 + threadIdx.x;
    if (i < n) p[i] = 0;
}
__global__ __launch_bounds__(256) void hist_k(const int* __restrict__ dst, int ne, int* deg) {
    int i = blockIdx.x * 256 + threadIdx.x;
    if (i < ne) atomicAdd(&deg[dst[i]], 1);
}
__global__ void scan_fast_k(const int* __restrict__ deg, int* __restrict__ rowptr,
                            int* __restrict__ cursor, int n) {
    __shared__ int ts[1024];
    int t = threadIdx.x;
    int C = (n + 1023) >> 10;
    int b0 = t * C, b1 = min(b0 + C, n);
    int s = 0;
    for (int i = b0; i < b1; i++) s += deg[i];
    ts[t] = s;
    __syncthreads();
    for (int off = 1; off < 1024; off <<= 1) {
        int v = (t >= off) ? ts[t - off] : 0;
        __syncthreads();
        ts[t] += v;
        __syncthreads();
    }
    int run = ts[t] - s;
    for (int i = b0; i < b1; i++) {
        cursor[i] = run;
        run += deg[i];
        rowptr[i + 1] = run;
    }
    if (t == 0) rowptr[0] = 0;
}
__global__ __launch_bounds__(256) void fill_k(const int* __restrict__ src, const int* __restrict__ dst,
                                              int ne, int* cursor, int* __restrict__ eidx) {
    int i = blockIdx.x * 256 + threadIdx.x;
    if (i < ne) {
        int p = atomicAdd(&cursor[dst[i]], 1);
        eidx[p] = src[i];
    }
}
__global__ void bounds_k(const int* __restrict__ gid, int n, int* __restrict__ gs) {
    int g = threadIdx.x;
    if (g > GNUM) return;
    int lo = 0, hi = n;
    while (lo < hi) {
        int mid = (lo + hi) >> 1;
        if (gid[mid] < g) lo = mid + 1; else hi = mid;
    }
    gs[g] = lo;
}

#define WSPLIT_TOT 557056
__global__ __launch_bounds__(256) void wsplit_all_k(const float* __restrict__ W_emb,
                                                    const float* __restrict__ W1,
                                                    const float* __restrict__ W2,
                                                    __nv_bfloat16* __restrict__ Wh,
                                                    __nv_bfloat16* __restrict__ Wl) {
    int i = blockIdx.x * 256 + threadIdx.x;
    if (i >= WSPLIT_TOT) return;
    const float* W;
    int idx, K;
    size_t base;
    if (i < 32768) {
        W = W_emb; idx = i; K = 128; base = W_EMB_OFF;
    } else if (i < 32768 + 262144) {
        int j = i - 32768;
        int l = j >> 16;
        W = W1 + (size_t)l * 65536; idx = j & 65535; K = 256; base = W1_OFF(l);
    } else {
        int j = i - 32768 - 262144;
        int l = j >> 16;
        W = W2 + (size_t)l * 65536; idx = j & 65535; K = 256; base = W2_OFF(l);
    }
    int k = idx >> 8, n = idx & 255;
    float x = W[idx];
    __nv_bfloat16 h = __float2bfloat16(x);
    float r = x - __bfloat162float(h);
    Wh[base + (size_t)n * K + k] = h;
    Wl[base + (size_t)n * K + k] = __float2bfloat16(r);
}

// ---------------- activation split (FOLD=1: relu(a*x+c) first) ----------------
template <int FOLD>
__global__ __launch_bounds__(256) void split_k(const float* __restrict__ T,
                                               const float* __restrict__ ac,
                                               __nv_bfloat16* __restrict__ Ah,
                                               __nv_bfloat16* __restrict__ Al, int n4) {
    int i = blockIdx.x * 256 + threadIdx.x;
    if (i >= n4) return;
    float4 v = ((const float4*)T)[i];
    if (FOLD) {
        int cb = (i * 4) & 255;
        float4 a = *(const float4*)&ac[cb];
        float4 c = *(const float4*)&ac[256 + cb];
        v.x = fmaxf(fmaf(a.x, v.x, c.x), 0.f);
        v.y = fmaxf(fmaf(a.y, v.y, c.y), 0.f);
        v.z = fmaxf(fmaf(a.z, v.z, c.z), 0.f);
        v.w = fmaxf(fmaf(a.w, v.w, c.w), 0.f);
    }
    uint2 hi = split4(v);
    uint2 lo = split4lo(v, hi);
    *(uint2*)(Ah + (size_t)i * 4) = hi;
    *(uint2*)(Al + (size_t)i * 4) = lo;
}

// ---------------- GIN aggregation (4-edge unrolled) -> split bf16 output ----------------
__global__ void agg_k(const float* __restrict__ H,
                      __nv_bfloat16* __restrict__ Ah, __nv_bfloat16* __restrict__ Al,
                      const int* __restrict__ rowptr, const int* __restrict__ eidx,
                      const float* __restrict__ eps, int l, int n) {
    int node = blockIdx.x * 8 + threadIdx.y;
    if (node >= n) return;
    int lane = threadIdx.x;
    const float4* h4 = (const float4*)(H + (size_t)node * DH);
    float ep = 1.0f + eps[l];
    float4 a0 = h4[lane];
    float4 a1 = h4[lane + 32];
    a0.x *= ep; a0.y *= ep; a0.z *= ep; a0.w *= ep;
    a1.x *= ep; a1.y *= ep; a1.z *= ep; a1.w *= ep;
    int beg = rowptr[node], end = rowptr[node + 1];
    int j = beg;
    for (; j + 3 < end; j += 4) {
        const float4* s0 = (const float4*)(H + (size_t)eidx[j] * DH);
        const float4* s1 = (const float4*)(H + (size_t)eidx[j + 1] * DH);
        const float4* s2 = (const float4*)(H + (size_t)eidx[j + 2] * DH);
        const float4* s3 = (const float4*)(H + (size_t)eidx[j + 3] * DH);
        float4 p00 = s0[lane], p01 = s0[lane + 32];
        float4 p10 = s1[lane], p11 = s1[lane + 32];
        float4 p20 = s2[lane], p21 = s2[lane + 32];
        float4 p30 = s3[lane], p31 = s3[lane + 32];
        a0.x += (p00.x + p10.x) + (p20.x + p30.x);
        a0.y += (p00.y + p10.y) + (p20.y + p30.y);
        a0.z += (p00.z + p10.z) + (p20.z + p30.z);
        a0.w += (p00.w + p10.w) + (p20.w + p30.w);
        a1.x += (p01.x + p11.x) + (p21.x + p31.x);
        a1.y += (p01.y + p11.y) + (p21.y + p31.y);
        a1.z += (p01.z + p11.z) + (p21.z + p31.z);
        a1.w += (p01.w + p11.w) + (p21.w + p31.w);
    }
    for (; j < end; j++) {
        const float4* sA = (const float4*)(H + (size_t)eidx[j] * DH);
        float4 pa0 = sA[lane], pa1 = sA[lane + 32];
        a0.x += pa0.x; a0.y += pa0.y; a0.z += pa0.z; a0.w += pa0.w;
        a1.x += pa1.x; a1.y += pa1.y; a1.z += pa1.z; a1.w += pa1.w;
    }
    uint2 h0 = split4(a0), h1 = split4(a1);
    uint2 l0 = split4lo(a0, h0), l1 = split4lo(a1, h1);
    size_t base = (size_t)node * DH + lane * 4;
    *(uint2*)(Ah + base) = h0;
    *(uint2*)(Ah + base + 128) = h1;
    *(uint2*)(Al + base) = l0;
    *(uint2*)(Al + base + 128) = l1;
}

// ---------------- all-bf16 mma.sync GEMM: 3-stage pipeline, merged hi/lo buffers ----------------
#define TSZ 8192
#define STG 32768
#define OFF_BIAS 98304
#define SMEM_GEMM (OFF_BIAS + 512)

__global__ __launch_bounds__(256, 2) void gemm_bf16_k(
    const __nv_bfloat16* __restrict__ A, uint32_t aLoB,
    const __nv_bfloat16* __restrict__ B, uint32_t bLoB,
    const float* __restrict__ bias, float* __restrict__ C, int M, int K)
{
    extern __shared__ char smem[];
    uint32_t sb = smem_u32(smem);
    int tid = threadIdx.x;
    int wid = tid >> 5, lane = tid & 31;
    int wm = wid >> 1, wn = wid & 1;
    int g = lane >> 2, tq = lane & 3;
    int m0 = blockIdx.x * 128, n0 = blockIdx.y * 128;
    int NC = K >> 5;

    if (tid < 32) ((float4*)(smem + OFF_BIAS))[tid] = ((const float4*)(bias + n0))[tid];

    int r1 = tid >> 2, q1 = tid & 3;
    uint32_t sw1 = swz((uint32_t)r1, (uint32_t)q1);
    int ar0 = min(m0 + r1, M - 1);
    int ar1 = min(m0 + r1 + 64, M - 1);
    const char* ag0 = (const char*)(A + (size_t)ar0 * K);
    const char* ag1 = (const char*)(A + (size_t)ar1 * K);
    const char* bg0 = (const char*)(B + (size_t)(n0 + r1) * K);
    const char* bg1 = (const char*)(B + (size_t)(n0 + r1 + 64) * K);

    auto issue = [&](int kc) {
        uint32_t bs = sb + (uint32_t)(kc % 3) * STG;
        int go = kc * 64 + q1 * 16;
        cp16(bs + sw1,                  ag0 + go);
        cp16(bs + sw1 + 4096,           ag1 + go);
        cp16(bs + TSZ + sw1,            ag0 + go + aLoB);
        cp16(bs + TSZ + sw1 + 4096,     ag1 + go + aLoB);
        cp16(bs + 2 * TSZ + sw1,        bg0 + go);
        cp16(bs + 2 * TSZ + sw1 + 4096, bg1 + go);
        cp16(bs + 3 * TSZ + sw1,        bg0 + go + bLoB);
        cp16(bs + 3 * TSZ + sw1 + 4096, bg1 + go + bLoB);
        CP_COMMIT();
    };

    uint32_t rA = (uint32_t)(wm * 32 + (lane & 15));
    uint32_t qA = (uint32_t)((lane >> 4) & 1);
    uint32_t aA0 = swz(rA, qA);
    uint32_t aA1 = swz(rA, qA + 2);
    uint32_t rB = (uint32_t)(wn * 64 + (lane & 7) + ((lane >> 4) & 1) * 8);
    uint32_t qB = (uint32_t)((lane >> 3) & 1);
    uint32_t bA0 = swz(rB, qB);
    uint32_t bA1 = swz(rB, qB + 2);

    float acc[2][8][4];
#pragma unroll
    for (int mt = 0; mt < 2; mt++)
#pragma unroll
        for (int nn = 0; nn < 8; nn++)
#pragma unroll
            for (int r = 0; r < 4; r++) acc[mt][nn][r] = 0.0f;

    issue(0);
    issue(1);

    for (int kc = 0; kc < NC; kc++) {
        if (kc + 1 < NC) { CP_WAIT1(); } else { CP_WAIT0(); }
        __syncthreads();
        if (kc + 2 < NC) issue(kc + 2);

        uint32_t st = sb + (uint32_t)(kc % 3) * STG;
#pragma unroll
        for (int ks = 0; ks < 2; ks++) {
            uint32_t aoff = st + (ks ? aA1 : aA0);
            uint32_t boff = st + 2 * TSZ + (ks ? bA1 : bA0);
            uint32_t ah[2][4], al[2][4];
#pragma unroll
            for (int mt = 0; mt < 2; mt++) {
                ldsm4(ah[mt][0], ah[mt][1], ah[mt][2], ah[mt][3], aoff + mt * 1024);
                ldsm4(al[mt][0], al[mt][1], al[mt][2], al[mt][3], aoff + TSZ + mt * 1024);
            }
#pragma unroll
            for (int np = 0; np < 4; np++) {
                uint32_t bb = boff + np * 1024;
                uint32_t bh0, bh1, bh2, bh3, bl0, bl1, bl2, bl3;
                ldsm4(bh0, bh1, bh2, bh3, bb);
                ldsm4(bl0, bl1, bl2, bl3, bb + TSZ);
                int nn = np * 2;
                mma16816(acc[0][nn], ah[0], bh0, bh1);
                mma16816(acc[1][nn], ah[1], bh0, bh1);
                mma16816(acc[0][nn], ah[0], bl0, bl1);
                mma16816(acc[1][nn], ah[1], bl0, bl1);
                mma16816(acc[0][nn], al[0], bh0, bh1);
                mma16816(acc[1][nn], al[1], bh0, bh1);
                mma16816(acc[0][nn + 1], ah[0], bh2, bh3);
                mma16816(acc[1][nn + 1], ah[1], bh2, bh3);
                mma16816(acc[0][nn + 1], ah[0], bl2, bl3);
                mma16816(acc[1][nn + 1], ah[1], bl2, bl3);
                mma16816(acc[0][nn + 1], al[0], bh2, bh3);
                mma16816(acc[1][nn + 1], al[1], bh2, bh3);
            }
        }
    }

    const float* biasS = (const float*)(smem + OFF_BIAS);
#pragma unroll
    for (int mt = 0; mt < 2; mt++) {
        int row = m0 + wm * 32 + mt * 16 + g;
#pragma unroll
        for (int nn = 0; nn < 8; nn++) {
            int colr = wn * 64 + nn * 8 + 2 * tq;
            float b0 = biasS[colr], b1 = biasS[colr + 1];
            int col = n0 + colr;
            if (row < M)
                *(float2*)&C[(size_t)row * 256 + col] =
                    make_float2(acc[mt][nn][0] + b0, acc[mt][nn][1] + b1);
            if (row + 8 < M)
                *(float2*)&C[(size_t)(row + 8) * 256 + col] =
                    make_float2(acc[mt][nn][2] + b0, acc[mt][nn][3] + b1);
        }
    }
}

// ---------------- column stats (4 independent row streams) ----------------
template <int TRANS>
__global__ void colstats_k(const float* __restrict__ T, const float* __restrict__ tac,
                           float* __restrict__ part, int M) {
    int c = threadIdx.x;
    int r0 = blockIdx.x * 256;
    float a = 0.f, b = 0.f;
    if (TRANS) { a = tac[c]; b = tac[256 + c]; }
    float s0 = 0.f, s1 = 0.f, s2 = 0.f, s3 = 0.f;
    float q0 = 0.f, q1 = 0.f, q2 = 0.f, q3 = 0.f;
    const float* base = T + c;
#pragma unroll 4
    for (int j = 0; j < 64; j++) {
        int r = r0 + j;
        float x0 = (r < M)       ? base[(size_t)r * DH]         : 0.f;
        float x1 = (r + 64 < M)  ? base[(size_t)(r + 64) * DH]  : 0.f;
        float x2 = (r + 128 < M) ? base[(size_t)(r + 128) * DH] : 0.f;
        float x3 = (r + 192 < M) ? base[(size_t)(r + 192) * DH] : 0.f;
        if (TRANS) {
            x0 = (r < M)       ? fmaxf(fmaf(a, x0, b), 0.f) : 0.f;
            x1 = (r + 64 < M)  ? fmaxf(fmaf(a, x1, b), 0.f) : 0.f;
            x2 = (r + 128 < M) ? fmaxf(fmaf(a, x2, b), 0.f) : 0.f;
            x3 = (r + 192 < M) ? fmaxf(fmaf(a, x3, b), 0.f) : 0.f;
        }
        s0 += x0; q0 += x0 * x0;
        s1 += x1; q1 += x1 * x1;
        s2 += x2; q2 += x2 * x2;
        s3 += x3; q3 += x3 * x3;
    }
    part[blockIdx.x * 512 + c] = (s0 + s1) + (s2 + s3);
    part[blockIdx.x * 512 + 256 + c] = (q0 + q1) + (q2 + q3);
}

__global__ void finalize_k(const float* __restrict__ part, int nb, int n,
                           const float* __restrict__ gamma, const float* __restrict__ beta,
                           float* __restrict__ ac) {
    __shared__ float sh[4][512];
    int c = threadIdx.x & 255;
    int seg = threadIdx.x >> 8;
    int b0 = (nb * seg) >> 2, b1 = (nb * (seg + 1)) >> 2;
    float s = 0.f, ss = 0.f;
    for (int b = b0; b < b1; b++) {
        s += part[b * 512 + c];
        ss += part[b * 512 + 256 + c];
    }
    sh[seg][c] = s;
    sh[seg][256 + c] = ss;
    __syncthreads();
    if (seg == 0) {
        float ts = (sh[0][c] + sh[1][c]) + (sh[2][c] + sh[3][c]);
        float tss = (sh[0][256 + c] + sh[1][256 + c]) + (sh[2][256 + c] + sh[3][256 + c]);
        float inv = 1.0f / (float)n;
        float m = ts * inv;
        float v = tss * inv - m * m;
        float a = gamma[c] * rsqrtf(v + BN_EPS);
        ac[c] = a;
        ac[256 + c] = beta[c] - a * m;
    }
}

__global__ __launch_bounds__(256) void update_k(float* __restrict__ H, const float* __restrict__ T2,
                                                const float* __restrict__ acA, const float* __restrict__ acG,
                                                int n4) {
    int i = blockIdx.x * 256 + threadIdx.x;
    if (i >= n4) return;
    int cb = (i * 4) & 255;
    float4 t  = ((const float4*)T2)[i];
    float4 aA = *(const float4*)&acA[cb];
    float4 cA = *(const float4*)&acA[256 + cb];
    float4 aG = *(const float4*)&acG[cb];
    float4 cG = *(const float4*)&acG[256 + cb];
    float4 h  = ((float4*)H)[i];
    h.x += fmaxf(aG.x * fmaxf(aA.x * t.x + cA.x, 0.f) + cG.x, 0.f);
    h.y += fmaxf(aG.y * fmaxf(aA.y * t.y + cA.y, 0.f) + cG.y, 0.f);
    h.z += fmaxf(aG.z * fmaxf(aA.z * t.z + cA.z, 0.f) + cG.z, 0.f);
    h.w += fmaxf(aG.w * fmaxf(aA.w * t.w + cA.w, 0.f) + cG.w, 0.f);
    ((float4*)H)[i] = h;
}

__global__ void readout_k(const float* __restrict__ H, const int* __restrict__ gs,
                          float* __restrict__ R) {
    int g = blockIdx.x;
    int c = threadIdx.x;
    int beg = gs[g], end = gs[g + 1];
    float s = 0.f;
    for (int i = beg; i < end; i++) s += H[(size_t)i * DH + c];
    R[g * DH + c] = s;
}

__global__ void predict_k(const float* __restrict__ Rg, const float* __restrict__ Rq,
                          const float* __restrict__ Wp1, const float* __restrict__ bp1,
                          const float* __restrict__ Wp2, const float* __restrict__ bp2,
                          float* __restrict__ out) {
    int g = blockIdx.x;
    int t = threadIdx.x;
    __shared__ float d[256];
    __shared__ float red[256];
    d[t] = fabsf(Rg[g * DH + t] - Rq[g * DH + t]);
    __syncthreads();
    float acc = bp1[t];
    for (int k = 0; k < 256; k++) acc += d[k] * Wp1[k * 256 + t];
    acc = fmaxf(acc, 0.f);
    red[t] = acc * Wp2[t];
    __syncthreads();
    for (int s = 128; s > 0; s >>= 1) {
        if (t < s) red[t] += red[t + s];
        __syncthreads();
    }
    if (t == 0) out[g] = red[0] + bp2[0];
}

// ---------------- host orchestration ----------------
struct Scratch {
    float *H, *T1, *T2, *part, *ac;
    __nv_bfloat16 *Ah, *Al;
    uint32_t aLoB;
    int *deg, *rowptr, *cursor, *eidx, *gstart;
};

static void build_csr(cudaStream_t st, const Scratch& sc, int n,
                      const int* src, const int* dst, int ne, const int* gid) {
    zero_int_k<<<(n + 256) / 256, 256, 0, st>>>(sc.deg, n + 1);
    hist_k<<<(ne + 255) / 256, 256, 0, st>>>(dst, ne, sc.deg);
    scan_fast_k<<<1, 1024, 0, st>>>(sc.deg, sc.rowptr, sc.cursor, n);
    fill_k<<<(ne + 255) / 256, 256, 0, st>>>(src, dst, ne, sc.cursor, sc.eidx);
    bounds_k<<<1, GNUM + 1, 0, st>>>(gid, n, sc.gstart);
}

static void run_layers(cudaStream_t st, const Scratch& sc, const __nv_bfloat16* Wbase,
                       int n, const float* eps,
                       const float* b1, const float* bn1_g, const float* bn1_b,
                       const float* b2, const float* bnA_g, const float* bnA_b,
                       const float* bnG_g, const float* bnG_b,
                       float* R) {
    int gx = (n + 127) / 128;
    dim3 gg(gx, 2);
    int sb = (n + 255) / 256;
    for (int l = 0; l < 4; l++) {
        int bo = l * 256;
        agg_k<<<(n + 7) / 8, dim3(32, 8), 0, st>>>(sc.H, sc.Ah, sc.Al, sc.rowptr, sc.eidx, eps, l, n);
        gemm_bf16_k<<<gg, 256, SMEM_GEMM, st>>>(sc.Ah, sc.aLoB, Wbase + W1_OFF(l), W_LO_B,
                                                b1 + bo, sc.T1, n, 256);
        colstats_k<0><<<sb, 256, 0, st>>>(sc.T1, nullptr, sc.part, n);
        finalize_k<<<1, 1024, 0, st>>>(sc.part, sb, n, bn1_g + bo, bn1_b + bo, sc.ac);
        split_k<1><<<(n * 64 + 255) / 256, 256, 0, st>>>(sc.T1, sc.ac, sc.Ah, sc.Al, n * 64);
        gemm_bf16_k<<<gg, 256, SMEM_GEMM, st>>>(sc.Ah, sc.aLoB, Wbase + W2_OFF(l), W_LO_B,
                                                b2 + bo, sc.T2, n, 256);
        colstats_k<0><<<sb, 256, 0, st>>>(sc.T2, nullptr, sc.part, n);
        finalize_k<<<1, 1024, 0, st>>>(sc.part, sb, n, bnA_g + bo, bnA_b + bo, sc.ac + 512);
        colstats_k<1><<<sb, 256, 0, st>>>(sc.T2, sc.ac + 512, sc.part, n);
        finalize_k<<<1, 1024, 0, st>>>(sc.part, sb, n, bnG_g + bo, bnG_b + bo, sc.ac + 1024);
        update_k<<<((n * 64) + 255) / 256, 256, 0, st>>>(sc.H, sc.T2, sc.ac + 512, sc.ac + 1024, n * 64);
    }
    readout_k<<<GNUM, 256, 0, st>>>(sc.H, sc.gstart, R);
}

extern "C" void kernel_launch(void* const* d_in, const int* in_sizes, int n_in,
                              void* d_out, int out_size) {
    const float* X     = (const float*)d_in[0];
    const float* X_q   = (const float*)d_in[2];
    const float* W_emb = (const float*)d_in[4];
    const float* b_emb = (const float*)d_in[5];
    const float* eps   = (const float*)d_in[6];
    const float* W1    = (const float*)d_in[7];
    const float* b1    = (const float*)d_in[8];
    const float* bn1_g = (const float*)d_in[9];
    const float* bn1_b = (const float*)d_in[10];
    const float* W2    = (const float*)d_in[11];
    const float* b2    = (const float*)d_in[12];
    const float* bnA_g = (const float*)d_in[13];
    const float* bnA_b = (const float*)d_in[14];
    const float* bnG_g = (const float*)d_in[15];
    const float* bnG_b = (const float*)d_in[16];
    const float* Wp1   = (const float*)d_in[17];
    const float* bp1   = (const float*)d_in[18];
    const float* Wp2   = (const float*)d_in[19];
    const float* bp2   = (const float*)d_in[20];
    const int* src_g   = (const int*)d_in[21];
    const int* dst_g   = (const int*)d_in[22];
    const int* gid_g   = (const int*)d_in[23];
    const int* src_q   = (const int*)d_in[24];
    const int* dst_q   = (const int*)d_in[25];
    const int* gid_q   = (const int*)d_in[26];

    int n_g = in_sizes[0] / 128;
    int e_g = in_sizes[21];
    int n_q = in_sizes[2] / 128;
    int e_q = in_sizes[24];

    Scratch sg, sq;
    __nv_bfloat16 *A2g, *A2q, *Wbase;
    cudaGetSymbolAddress((void**)&sg.H, g_H);
    cudaGetSymbolAddress((void**)&sg.T1, g_T1);
    cudaGetSymbolAddress((void**)&sg.T2, g_T2);
    cudaGetSymbolAddress((void**)&sg.part, g_part);
    cudaGetSymbolAddress((void**)&sg.ac, g_ac);
    cudaGetSymbolAddress((void**)&A2g, g_A2);
    cudaGetSymbolAddress((void**)&sg.deg, g_deg);
    cudaGetSymbolAddress((void**)&sg.rowptr, g_rowptr);
    cudaGetSymbolAddress((void**)&sg.cursor, g_cursor);
    cudaGetSymbolAddress((void**)&sg.eidx, g_eidx);
    cudaGetSymbolAddress((void**)&sg.gstart, g_gstart);
    cudaGetSymbolAddress((void**)&sq.H, q_H);
    cudaGetSymbolAddress((void**)&sq.T1, q_T1);
    cudaGetSymbolAddress((void**)&sq.T2, q_T2);
    cudaGetSymbolAddress((void**)&sq.part, q_part);
    cudaGetSymbolAddress((void**)&sq.ac, q_ac);
    cudaGetSymbolAddress((void**)&A2q, q_A2);
    cudaGetSymbolAddress((void**)&sq.deg, q_deg);
    cudaGetSymbolAddress((void**)&sq.rowptr, q_rowptr);
    cudaGetSymbolAddress((void**)&sq.cursor, q_cursor);
    cudaGetSymbolAddress((void**)&sq.eidx, q_eidx);
    cudaGetSymbolAddress((void**)&sq.gstart, q_gstart);
    cudaGetSymbolAddress((void**)&Wbase, g_W2);
    float* R;
    cudaGetSymbolAddress((void**)&R, g_R);

    sg.Ah = A2g; sg.Al = A2g + (size_t)NMAX * DH; sg.aLoB = A_LO_B_G;
    sq.Ah = A2q; sq.Al = A2q + (size_t)NQMAX * DH; sq.aLoB = A_LO_B_Q;

    cudaFuncSetAttribute(gemm_bf16_k, cudaFuncAttributeMaxDynamicSharedMemorySize, SMEM_GEMM);

    // single extra stream (R9-R11 proven footprint)
    cudaStream_t s2;
    cudaEvent_t evFork, evJoin, evCsrG;
    cudaStreamCreateWithFlags(&s2, cudaStreamNonBlocking);
    cudaEventCreateWithFlags(&evFork, cudaEventDisableTiming);
    cudaEventCreateWithFlags(&evJoin, cudaEventDisableTiming);
    cudaEventCreateWithFlags(&evCsrG, cudaEventDisableTiming);

    wsplit_all_k<<<(WSPLIT_TOT + 255) / 256, 256>>>(W_emb, W1, W2,
                                                    Wbase, Wbase + WTOT);

    cudaEventRecord(evFork, 0);
    cudaStreamWaitEvent(s2, evFork, 0);

    // s2: g-CSR first (overlaps g-stream's split + emb GEMM), then q pipeline
    build_csr(s2, sg, n_g, src_g, dst_g, e_g, gid_g);
    cudaEventRecord(evCsrG, s2);

    // g-stream: split + emb GEMM, then wait for CSR-g, then layers
    split_k<0><<<(n_g * 32 + 255) / 256, 256>>>(X, nullptr, sg.Ah, sg.Al, n_g * 32);
    gemm_bf16_k<<<dim3((n_g + 127) / 128, 2), 256, SMEM_GEMM>>>(
        sg.Ah, sg.aLoB, Wbase + W_EMB_OFF, W_LO_B, b_emb, sg.H, n_g, 128);
    cudaStreamWaitEvent((cudaStream_t)0, evCsrG, 0);
    run_layers((cudaStream_t)0, sg, Wbase, n_g, eps,
               b1, bn1_g, bn1_b, b2, bnA_g, bnA_b, bnG_g, bnG_b, R);

    // s2: q pipeline (CSR inline on s2)
    build_csr(s2, sq, n_q, src_q, dst_q, e_q, gid_q);
    split_k<0><<<(n_q * 32 + 255) / 256, 256, 0, s2>>>(X_q, nullptr, sq.Ah, sq.Al, n_q * 32);
    gemm_bf16_k<<<dim3((n_q + 127) / 128, 2), 256, SMEM_GEMM, s2>>>(
        sq.Ah, sq.aLoB, Wbase + W_EMB_OFF, W_LO_B, b_emb, sq.H, n_q, 128);
    run_layers(s2, sq, Wbase, n_q, eps,
               b1, bn1_g, bn1_b, b2, bnA_g, bnA_b, bnG_g, bnG_b, R + GNUM * DH);

    cudaEventRecord(evJoin, s2);
    cudaStreamWaitEvent((cudaStream_t)0, evJoin, 0);

    predict_k<<<GNUM, 256>>>(R, R + GNUM * DH, Wp1, bp1, Wp2, bp2, (float*)d_out);
}

// round 14
// speedup vs baseline: 1.0661x; 1.0661x over previous
#include <cuda_runtime.h>
#include <cuda_bf16.h>
#include <cstdint>

#define DH 256
#define NMAX 50000
#define EMAX 800000
#define NQMAX 12500
#define EQMAX 200000
#define GNUM 64
#define BN_EPS 1e-5f

// ---------------- scratch (static device memory) ----------------
__device__ __align__(16) float g_H [NMAX * DH];
__device__ __align__(16) float g_T1[NMAX * DH];
__device__ __align__(16) float g_T2[NMAX * DH];
__device__ __align__(16) __nv_bfloat16 g_A2[2 * NMAX * DH];   // [hi | lo] merged
__device__ int   g_deg[NMAX + 1];
__device__ int   g_rowptr[NMAX + 1];
__device__ int   g_cursor[NMAX];
__device__ int   g_eidx[EMAX];
__device__ int   g_bsum[256];
__device__ __align__(16) float g_part[256 * 512];
__device__ __align__(16) float g_ac[3 * 512];
__device__ int   g_gstart[GNUM + 1];
__device__ __align__(16) float q_H [NQMAX * DH];
__device__ __align__(16) float q_T1[NQMAX * DH];
__device__ __align__(16) float q_T2[NQMAX * DH];
__device__ __align__(16) __nv_bfloat16 q_A2[2 * NQMAX * DH];  // [hi | lo] merged
__device__ int   q_deg[NQMAX + 1];
__device__ int   q_rowptr[NQMAX + 1];
__device__ int   q_cursor[NQMAX];
__device__ int   q_eidx[EQMAX];
__device__ int   q_bsum[256];
__device__ __align__(16) float q_part[256 * 512];
__device__ __align__(16) float q_ac[3 * 512];
__device__ int   q_gstart[GNUM + 1];
__device__ __align__(16) float g_R[2 * GNUM * DH];

#define W_EMB_OFF 0
#define W1_OFF(l) (32768 + (l) * 65536)
#define W2_OFF(l) (32768 + 262144 + (l) * 65536)
#define WTOT      (32768 + 524288)
__device__ __align__(16) __nv_bfloat16 g_W2[2 * WTOT];        // [hi | lo] merged

#define A_LO_B_G (NMAX * DH * 2)
#define A_LO_B_Q (NQMAX * DH * 2)
#define W_LO_B   (WTOT * 2)

// ---------------- helpers ----------------
__device__ __forceinline__ uint32_t smem_u32(const void* p) {
    return (uint32_t)__cvta_generic_to_shared(p);
}
__device__ __forceinline__ void cp16(uint32_t dst, const void* src) {
    asm volatile("cp.async.cg.shared.global [%0], [%1], 16;" :: "r"(dst), "l"(src) : "memory");
}
#define CP_COMMIT() asm volatile("cp.async.commit_group;" ::: "memory")
#define CP_WAIT1()  asm volatile("cp.async.wait_group 1;" ::: "memory")
#define CP_WAIT0()  asm volatile("cp.async.wait_group 0;" ::: "memory")

__device__ __forceinline__ void mma16816(float* d, const uint32_t* a, uint32_t b0, uint32_t b1) {
    asm volatile(
        "mma.sync.aligned.m16n8k16.row.col.f32.bf16.bf16.f32 "
        "{%0,%1,%2,%3}, {%4,%5,%6,%7}, {%8,%9}, {%0,%1,%2,%3};"
        : "+f"(d[0]), "+f"(d[1]), "+f"(d[2]), "+f"(d[3])
        : "r"(a[0]), "r"(a[1]), "r"(a[2]), "r"(a[3]), "r"(b0), "r"(b1));
}
__device__ __forceinline__ void ldsm4(uint32_t& r0, uint32_t& r1, uint32_t& r2, uint32_t& r3,
                                      uint32_t addr) {
    asm volatile("ldmatrix.sync.aligned.m8n8.x4.shared.b16 {%0,%1,%2,%3}, [%4];"
                 : "=r"(r0), "=r"(r1), "=r"(r2), "=r"(r3) : "r"(addr));
}

// 64B-pitch conflict-free tile swizzle (verified R10/R11)
__device__ __forceinline__ uint32_t swz(uint32_t r, uint32_t q) {
    return (r >> 1) * 128 + (((r & 1) * 4 + (q ^ ((r >> 1) & 3))) << 4);
}

__device__ __forceinline__ uint2 split4(float4 v) {
    __nv_bfloat16 hx = __float2bfloat16(v.x), hy = __float2bfloat16(v.y);
    __nv_bfloat16 hz = __float2bfloat16(v.z), hw = __float2bfloat16(v.w);
    __nv_bfloat162 p0 = __halves2bfloat162(hx, hy);
    __nv_bfloat162 p1 = __halves2bfloat162(hz, hw);
    return make_uint2(*(uint32_t*)&p0, *(uint32_t*)&p1);
}
__device__ __forceinline__ uint2 split4lo(float4 v, uint2 hi) {
    __nv_bfloat162 h0 = *(__nv_bfloat162*)&hi.x;
    __nv_bfloat162 h1 = *(__nv_bfloat162*)&hi.y;
    __nv_bfloat16 lx = __float2bfloat16(v.x - __bfloat162float(__low2bfloat16(h0)));
    __nv_bfloat16 ly = __float2bfloat16(v.y - __bfloat162float(__high2bfloat16(h0)));
    __nv_bfloat16 lz = __float2bfloat16(v.z - __bfloat162float(__low2bfloat16(h1)));
    __nv_bfloat16 lw = __float2bfloat16(v.w - __bfloat162float(__high2bfloat16(h1)));
    __nv_bfloat162 p0 = __halves2bfloat162(lx, ly);
    __nv_bfloat162 p1 = __halves2bfloat162(lz, lw);
    return make_uint2(*(uint32_t*)&p0, *(uint32_t*)&p1);
}

// ---------------- small utility kernels ----------------
__global__ __launch_bounds__(256) void zero_int_k(int* p, int n) {
    int i = blockIdx.x * 256 + threadIdx.x;
    if (i < n) p[i] = 0;
}
__global__ __launch_bounds__(256) void hist_k(const int* __restrict__ dst, int ne, int* deg) {
    int i = blockIdx.x * 256 + threadIdx.x;
    if (i < ne) atomicAdd(&deg[dst[i]], 1);
}
// hierarchical scan: per-block sums -> tiny scan -> expand (contention-robust)
__global__ __launch_bounds__(256) void blocksum_k(const int* __restrict__ deg,
                                                  int* __restrict__ bsum, int n) {
    __shared__ int sh[256];
    int t = threadIdx.x;
    int i = blockIdx.x * 256 + t;
    sh[t] = (i < n) ? deg[i] : 0;
    __syncthreads();
    for (int s = 128; s > 0; s >>= 1) {
        if (t < s) sh[t] += sh[t + s];
        __syncthreads();
    }
    if (t == 0) bsum[blockIdx.x] = sh[0];
}
__global__ void scanb_k(int* __restrict__ bsum, int nb) {
    __shared__ int sh[256];
    int t = threadIdx.x;
    int v = (t < nb) ? bsum[t] : 0;
    sh[t] = v;
    __syncthreads();
    for (int off = 1; off < 256; off <<= 1) {
        int u = (t >= off) ? sh[t - off] : 0;
        __syncthreads();
        sh[t] += u;
        __syncthreads();
    }
    if (t < nb) bsum[t] = sh[t] - v;   // exclusive prefix of block sums
}
__global__ __launch_bounds__(256) void expand_k(const int* __restrict__ deg,
                                                const int* __restrict__ bsumx,
                                                int* __restrict__ rowptr,
                                                int* __restrict__ cursor, int n) {
    __shared__ int sh[256];
    int t = threadIdx.x;
    int i = blockIdx.x * 256 + t;
    int v = (i < n) ? deg[i] : 0;
    sh[t] = v;
    __syncthreads();
    for (int off = 1; off < 256; off <<= 1) {
        int u = (t >= off) ? sh[t - off] : 0;
        __syncthreads();
        sh[t] += u;
        __syncthreads();
    }
    if (i < n) {
        int incl = sh[t] + bsumx[blockIdx.x];
        cursor[i] = incl - v;
        rowptr[i + 1] = incl;
    }
    if (i == 0) rowptr[0] = 0;
}
__global__ __launch_bounds__(256) void fill_k(const int* __restrict__ src, const int* __restrict__ dst,
                                              int ne, int* cursor, int* __restrict__ eidx) {
    int i = blockIdx.x * 256 + threadIdx.x;
    if (i < ne) {
        int p = atomicAdd(&cursor[dst[i]], 1);
        eidx[p] = src[i];
    }
}
__global__ void bounds_k(const int* __restrict__ gid, int n, int* __restrict__ gs) {
    int g = threadIdx.x;
    if (g > GNUM) return;
    int lo = 0, hi = n;
    while (lo < hi) {
        int mid = (lo + hi) >> 1;
        if (gid[mid] < g) lo = mid + 1; else hi = mid;
    }
    gs[g] = lo;
}

#define WSPLIT_TOT 557056
__global__ __launch_bounds__(256) void wsplit_all_k(const float* __restrict__ W_emb,
                                                    const float* __restrict__ W1,
                                                    const float* __restrict__ W2,
                                                    __nv_bfloat16* __restrict__ Wh,
                                                    __nv_bfloat16* __restrict__ Wl) {
    int i = blockIdx.x * 256 + threadIdx.x;
    if (i >= WSPLIT_TOT) return;
    const float* W;
    int idx, K;
    size_t base;
    if (i < 32768) {
        W = W_emb; idx = i; K = 128; base = W_EMB_OFF;
    } else if (i < 32768 + 262144) {
        int j = i - 32768;
        int l = j >> 16;
        W = W1 + (size_t)l * 65536; idx = j & 65535; K = 256; base = W1_OFF(l);
    } else {
        int j = i - 32768 - 262144;
        int l = j >> 16;
        W = W2 + (size_t)l * 65536; idx = j & 65535; K = 256; base = W2_OFF(l);
    }
    int k = idx >> 8, n = idx & 255;
    float x = W[idx];
    __nv_bfloat16 h = __float2bfloat16(x);
    float r = x - __bfloat162float(h);
    Wh[base + (size_t)n * K + k] = h;
    Wl[base + (size_t)n * K + k] = __float2bfloat16(r);
}

// ---------------- activation split (FOLD=1: relu(a*x+c) first) ----------------
template <int FOLD>
__global__ __launch_bounds__(256) void split_k(const float* __restrict__ T,
                                               const float* __restrict__ ac,
                                               __nv_bfloat16* __restrict__ Ah,
                                               __nv_bfloat16* __restrict__ Al, int n4) {
    int i = blockIdx.x * 256 + threadIdx.x;
    if (i >= n4) return;
    float4 v = ((const float4*)T)[i];
    if (FOLD) {
        int cb = (i * 4) & 255;
        float4 a = *(const float4*)&ac[cb];
        float4 c = *(const float4*)&ac[256 + cb];
        v.x = fmaxf(fmaf(a.x, v.x, c.x), 0.f);
        v.y = fmaxf(fmaf(a.y, v.y, c.y), 0.f);
        v.z = fmaxf(fmaf(a.z, v.z, c.z), 0.f);
        v.w = fmaxf(fmaf(a.w, v.w, c.w), 0.f);
    }
    uint2 hi = split4(v);
    uint2 lo = split4lo(v, hi);
    *(uint2*)(Ah + (size_t)i * 4) = hi;
    *(uint2*)(Al + (size_t)i * 4) = lo;
}

// ---------------- GIN aggregation (4-edge unrolled) -> split bf16 output ----------------
__global__ void agg_k(const float* __restrict__ H,
                      __nv_bfloat16* __restrict__ Ah, __nv_bfloat16* __restrict__ Al,
                      const int* __restrict__ rowptr, const int* __restrict__ eidx,
                      const float* __restrict__ eps, int l, int n) {
    int node = blockIdx.x * 8 + threadIdx.y;
    if (node >= n) return;
    int lane = threadIdx.x;
    const float4* h4 = (const float4*)(H + (size_t)node * DH);
    float ep = 1.0f + eps[l];
    float4 a0 = h4[lane];
    float4 a1 = h4[lane + 32];
    a0.x *= ep; a0.y *= ep; a0.z *= ep; a0.w *= ep;
    a1.x *= ep; a1.y *= ep; a1.z *= ep; a1.w *= ep;
    int beg = rowptr[node], end = rowptr[node + 1];
    int j = beg;
    for (; j + 3 < end; j += 4) {
        const float4* s0 = (const float4*)(H + (size_t)eidx[j] * DH);
        const float4* s1 = (const float4*)(H + (size_t)eidx[j + 1] * DH);
        const float4* s2 = (const float4*)(H + (size_t)eidx[j + 2] * DH);
        const float4* s3 = (const float4*)(H + (size_t)eidx[j + 3] * DH);
        float4 p00 = s0[lane], p01 = s0[lane + 32];
        float4 p10 = s1[lane], p11 = s1[lane + 32];
        float4 p20 = s2[lane], p21 = s2[lane + 32];
        float4 p30 = s3[lane], p31 = s3[lane + 32];
        a0.x += (p00.x + p10.x) + (p20.x + p30.x);
        a0.y += (p00.y + p10.y) + (p20.y + p30.y);
        a0.z += (p00.z + p10.z) + (p20.z + p30.z);
        a0.w += (p00.w + p10.w) + (p20.w + p30.w);
        a1.x += (p01.x + p11.x) + (p21.x + p31.x);
        a1.y += (p01.y + p11.y) + (p21.y + p31.y);
        a1.z += (p01.z + p11.z) + (p21.z + p31.z);
        a1.w += (p01.w + p11.w) + (p21.w + p31.w);
    }
    for (; j < end; j++) {
        const float4* sA = (const float4*)(H + (size_t)eidx[j] * DH);
        float4 pa0 = sA[lane], pa1 = sA[lane + 32];
        a0.x += pa0.x; a0.y += pa0.y; a0.z += pa0.z; a0.w += pa0.w;
        a1.x += pa1.x; a1.y += pa1.y; a1.z += pa1.z; a1.w += pa1.w;
    }
    uint2 h0 = split4(a0), h1 = split4(a1);
    uint2 l0 = split4lo(a0, h0), l1 = split4lo(a1, h1);
    size_t base = (size_t)node * DH + lane * 4;
    *(uint2*)(Ah + base) = h0;
    *(uint2*)(Ah + base + 128) = h1;
    *(uint2*)(Al + base) = l0;
    *(uint2*)(Al + base + 128) = l1;
}

// ---------------- all-bf16 mma.sync GEMM: 3-stage pipeline, merged hi/lo buffers ----------------
#define TSZ 8192
#define STG 32768
#define OFF_BIAS 98304
#define SMEM_GEMM (OFF_BIAS + 512)

__global__ __launch_bounds__(256, 2) void gemm_bf16_k(
    const __nv_bfloat16* __restrict__ A, uint32_t aLoB,
    const __nv_bfloat16* __restrict__ B, uint32_t bLoB,
    const float* __restrict__ bias, float* __restrict__ C, int M, int K)
{
    extern __shared__ char smem[];
    uint32_t sb = smem_u32(smem);
    int tid = threadIdx.x;
    int wid = tid >> 5, lane = tid & 31;
    int wm = wid >> 1, wn = wid & 1;
    int g = lane >> 2, tq = lane & 3;
    int m0 = blockIdx.x * 128, n0 = blockIdx.y * 128;
    int NC = K >> 5;

    if (tid < 32) ((float4*)(smem + OFF_BIAS))[tid] = ((const float4*)(bias + n0))[tid];

    int r1 = tid >> 2, q1 = tid & 3;
    uint32_t sw1 = swz((uint32_t)r1, (uint32_t)q1);
    int ar0 = min(m0 + r1, M - 1);
    int ar1 = min(m0 + r1 + 64, M - 1);
    const char* ag0 = (const char*)(A + (size_t)ar0 * K);
    const char* ag1 = (const char*)(A + (size_t)ar1 * K);
    const char* bg0 = (const char*)(B + (size_t)(n0 + r1) * K);
    const char* bg1 = (const char*)(B + (size_t)(n0 + r1 + 64) * K);

    auto issue = [&](int kc) {
        uint32_t bs = sb + (uint32_t)(kc % 3) * STG;
        int go = kc * 64 + q1 * 16;
        cp16(bs + sw1,                  ag0 + go);
        cp16(bs + sw1 + 4096,           ag1 + go);
        cp16(bs + TSZ + sw1,            ag0 + go + aLoB);
        cp16(bs + TSZ + sw1 + 4096,     ag1 + go + aLoB);
        cp16(bs + 2 * TSZ + sw1,        bg0 + go);
        cp16(bs + 2 * TSZ + sw1 + 4096, bg1 + go);
        cp16(bs + 3 * TSZ + sw1,        bg0 + go + bLoB);
        cp16(bs + 3 * TSZ + sw1 + 4096, bg1 + go + bLoB);
        CP_COMMIT();
    };

    uint32_t rA = (uint32_t)(wm * 32 + (lane & 15));
    uint32_t qA = (uint32_t)((lane >> 4) & 1);
    uint32_t aA0 = swz(rA, qA);
    uint32_t aA1 = swz(rA, qA + 2);
    uint32_t rB = (uint32_t)(wn * 64 + (lane & 7) + ((lane >> 4) & 1) * 8);
    uint32_t qB = (uint32_t)((lane >> 3) & 1);
    uint32_t bA0 = swz(rB, qB);
    uint32_t bA1 = swz(rB, qB + 2);

    float acc[2][8][4];
#pragma unroll
    for (int mt = 0; mt < 2; mt++)
#pragma unroll
        for (int nn = 0; nn < 8; nn++)
#pragma unroll
            for (int r = 0; r < 4; r++) acc[mt][nn][r] = 0.0f;

    issue(0);
    issue(1);

    for (int kc = 0; kc < NC; kc++) {
        if (kc + 1 < NC) { CP_WAIT1(); } else { CP_WAIT0(); }
        __syncthreads();
        if (kc + 2 < NC) issue(kc + 2);

        uint32_t st = sb + (uint32_t)(kc % 3) * STG;
#pragma unroll
        for (int ks = 0; ks < 2; ks++) {
            uint32_t aoff = st + (ks ? aA1 : aA0);
            uint32_t boff = st + 2 * TSZ + (ks ? bA1 : bA0);
            uint32_t ah[2][4], al[2][4];
#pragma unroll
            for (int mt = 0; mt < 2; mt++) {
                ldsm4(ah[mt][0], ah[mt][1], ah[mt][2], ah[mt][3], aoff + mt * 1024);
                ldsm4(al[mt][0], al[mt][1], al[mt][2], al[mt][3], aoff + TSZ + mt * 1024);
            }
#pragma unroll
            for (int np = 0; np < 4; np++) {
                uint32_t bb = boff + np * 1024;
                uint32_t bh0, bh1, bh2, bh3, bl0, bl1, bl2, bl3;
                ldsm4(bh0, bh1, bh2, bh3, bb);
                ldsm4(bl0, bl1, bl2, bl3, bb + TSZ);
                int nn = np * 2;
                mma16816(acc[0][nn], ah[0], bh0, bh1);
                mma16816(acc[1][nn], ah[1], bh0, bh1);
                mma16816(acc[0][nn], ah[0], bl0, bl1);
                mma16816(acc[1][nn], ah[1], bl0, bl1);
                mma16816(acc[0][nn], al[0], bh0, bh1);
                mma16816(acc[1][nn], al[1], bh0, bh1);
                mma16816(acc[0][nn + 1], ah[0], bh2, bh3);
                mma16816(acc[1][nn + 1], ah[1], bh2, bh3);
                mma16816(acc[0][nn + 1], ah[0], bl2, bl3);
                mma16816(acc[1][nn + 1], ah[1], bl2, bl3);
                mma16816(acc[0][nn + 1], al[0], bh2, bh3);
                mma16816(acc[1][nn + 1], al[1], bh2, bh3);
            }
        }
    }

    const float* biasS = (const float*)(smem + OFF_BIAS);
#pragma unroll
    for (int mt = 0; mt < 2; mt++) {
        int row = m0 + wm * 32 + mt * 16 + g;
#pragma unroll
        for (int nn = 0; nn < 8; nn++) {
            int colr = wn * 64 + nn * 8 + 2 * tq;
            float b0 = biasS[colr], b1 = biasS[colr + 1];
            int col = n0 + colr;
            if (row < M)
                *(float2*)&C[(size_t)row * 256 + col] =
                    make_float2(acc[mt][nn][0] + b0, acc[mt][nn][1] + b1);
            if (row + 8 < M)
                *(float2*)&C[(size_t)(row + 8) * 256 + col] =
                    make_float2(acc[mt][nn][2] + b0, acc[mt][nn][3] + b1);
        }
    }
}

// ---------------- column stats (4 independent row streams) ----------------
template <int TRANS>
__global__ void colstats_k(const float* __restrict__ T, const float* __restrict__ tac,
                           float* __restrict__ part, int M) {
    int c = threadIdx.x;
    int r0 = blockIdx.x * 256;
    float a = 0.f, b = 0.f;
    if (TRANS) { a = tac[c]; b = tac[256 + c]; }
    float s0 = 0.f, s1 = 0.f, s2 = 0.f, s3 = 0.f;
    float q0 = 0.f, q1 = 0.f, q2 = 0.f, q3 = 0.f;
    const float* base = T + c;
#pragma unroll 4
    for (int j = 0; j < 64; j++) {
        int r = r0 + j;
        float x0 = (r < M)       ? base[(size_t)r * DH]         : 0.f;
        float x1 = (r + 64 < M)  ? base[(size_t)(r + 64) * DH]  : 0.f;
        float x2 = (r + 128 < M) ? base[(size_t)(r + 128) * DH] : 0.f;
        float x3 = (r + 192 < M) ? base[(size_t)(r + 192) * DH] : 0.f;
        if (TRANS) {
            x0 = (r < M)       ? fmaxf(fmaf(a, x0, b), 0.f) : 0.f;
            x1 = (r + 64 < M)  ? fmaxf(fmaf(a, x1, b), 0.f) : 0.f;
            x2 = (r + 128 < M) ? fmaxf(fmaf(a, x2, b), 0.f) : 0.f;
            x3 = (r + 192 < M) ? fmaxf(fmaf(a, x3, b), 0.f) : 0.f;
        }
        s0 += x0; q0 += x0 * x0;
        s1 += x1; q1 += x1 * x1;
        s2 += x2; q2 += x2 * x2;
        s3 += x3; q3 += x3 * x3;
    }
    part[blockIdx.x * 512 + c] = (s0 + s1) + (s2 + s3);
    part[blockIdx.x * 512 + 256 + c] = (q0 + q1) + (q2 + q3);
}

__global__ void finalize_k(const float* __restrict__ part, int nb, int n,
                           const float* __restrict__ gamma, const float* __restrict__ beta,
                           float* __restrict__ ac) {
    __shared__ float sh[4][512];
    int c = threadIdx.x & 255;
    int seg = threadIdx.x >> 8;
    int b0 = (nb * seg) >> 2, b1 = (nb * (seg + 1)) >> 2;
    float s = 0.f, ss = 0.f;
    for (int b = b0; b < b1; b++) {
        s += part[b * 512 + c];
        ss += part[b * 512 + 256 + c];
    }
    sh[seg][c] = s;
    sh[seg][256 + c] = ss;
    __syncthreads();
    if (seg == 0) {
        float ts = (sh[0][c] + sh[1][c]) + (sh[2][c] + sh[3][c]);
        float tss = (sh[0][256 + c] + sh[1][256 + c]) + (sh[2][256 + c] + sh[3][256 + c]);
        float inv = 1.0f / (float)n;
        float m = ts * inv;
        float v = tss * inv - m * m;
        float a = gamma[c] * rsqrtf(v + BN_EPS);
        ac[c] = a;
        ac[256 + c] = beta[c] - a * m;
    }
}

__global__ __launch_bounds__(256) void update_k(float* __restrict__ H, const float* __restrict__ T2,
                                                const float* __restrict__ acA, const float* __restrict__ acG,
                                                int n4) {
    int i = blockIdx.x * 256 + threadIdx.x;
    if (i >= n4) return;
    int cb = (i * 4) & 255;
    float4 t  = ((const float4*)T2)[i];
    float4 aA = *(const float4*)&acA[cb];
    float4 cA = *(const float4*)&acA[256 + cb];
    float4 aG = *(const float4*)&acG[cb];
    float4 cG = *(const float4*)&acG[256 + cb];
    float4 h  = ((float4*)H)[i];
    h.x += fmaxf(aG.x * fmaxf(aA.x * t.x + cA.x, 0.f) + cG.x, 0.f);
    h.y += fmaxf(aG.y * fmaxf(aA.y * t.y + cA.y, 0.f) + cG.y, 0.f);
    h.z += fmaxf(aG.z * fmaxf(aA.z * t.z + cA.z, 0.f) + cG.z, 0.f);
    h.w += fmaxf(aG.w * fmaxf(aA.w * t.w + cA.w, 0.f) + cG.w, 0.f);
    ((float4*)H)[i] = h;
}

__global__ void readout_k(const float* __restrict__ H, const int* __restrict__ gs,
                          float* __restrict__ R) {
    int g = blockIdx.x;
    int c = threadIdx.x;
    int beg = gs[g], end = gs[g + 1];
    float s = 0.f;
    for (int i = beg; i < end; i++) s += H[(size_t)i * DH + c];
    R[g * DH + c] = s;
}

__global__ void predict_k(const float* __restrict__ Rg, const float* __restrict__ Rq,
                          const float* __restrict__ Wp1, const float* __restrict__ bp1,
                          const float* __restrict__ Wp2, const float* __restrict__ bp2,
                          float* __restrict__ out) {
    int g = blockIdx.x;
    int t = threadIdx.x;
    __shared__ float d[256];
    __shared__ float red[256];
    d[t] = fabsf(Rg[g * DH + t] - Rq[g * DH + t]);
    __syncthreads();
    float acc = bp1[t];
    for (int k = 0; k < 256; k++) acc += d[k] * Wp1[k * 256 + t];
    acc = fmaxf(acc, 0.f);
    red[t] = acc * Wp2[t];
    __syncthreads();
    for (int s = 128; s > 0; s >>= 1) {
        if (t < s) red[t] += red[t + s];
        __syncthreads();
    }
    if (t == 0) out[g] = red[0] + bp2[0];
}

// ---------------- host orchestration ----------------
struct Scratch {
    float *H, *T1, *T2, *part, *ac;
    __nv_bfloat16 *Ah, *Al;
    uint32_t aLoB;
    int *deg, *rowptr, *cursor, *eidx, *bsum, *gstart;
};

static void build_csr(cudaStream_t st, const Scratch& sc, int n,
                      const int* src, const int* dst, int ne, const int* gid) {
    int nb = (n + 255) / 256;
    zero_int_k<<<(n + 256) / 256, 256, 0, st>>>(sc.deg, n + 1);
    hist_k<<<(ne + 255) / 256, 256, 0, st>>>(dst, ne, sc.deg);
    blocksum_k<<<nb, 256, 0, st>>>(sc.deg, sc.bsum, n);
    scanb_k<<<1, 256, 0, st>>>(sc.bsum, nb);
    expand_k<<<nb, 256, 0, st>>>(sc.deg, sc.bsum, sc.rowptr, sc.cursor, n);
    fill_k<<<(ne + 255) / 256, 256, 0, st>>>(src, dst, ne, sc.cursor, sc.eidx);
    bounds_k<<<1, GNUM + 1, 0, st>>>(gid, n, sc.gstart);
}

static void run_layers(cudaStream_t st, const Scratch& sc, const __nv_bfloat16* Wbase,
                       int n, const float* eps,
                       const float* b1, const float* bn1_g, const float* bn1_b,
                       const float* b2, const float* bnA_g, const float* bnA_b,
                       const float* bnG_g, const float* bnG_b,
                       float* R) {
    int gx = (n + 127) / 128;
    dim3 gg(gx, 2);
    int sb = (n + 255) / 256;
    for (int l = 0; l < 4; l++) {
        int bo = l * 256;
        agg_k<<<(n + 7) / 8, dim3(32, 8), 0, st>>>(sc.H, sc.Ah, sc.Al, sc.rowptr, sc.eidx, eps, l, n);
        gemm_bf16_k<<<gg, 256, SMEM_GEMM, st>>>(sc.Ah, sc.aLoB, Wbase + W1_OFF(l), W_LO_B,
                                                b1 + bo, sc.T1, n, 256);
        colstats_k<0><<<sb, 256, 0, st>>>(sc.T1, nullptr, sc.part, n);
        finalize_k<<<1, 1024, 0, st>>>(sc.part, sb, n, bn1_g + bo, bn1_b + bo, sc.ac);
        split_k<1><<<(n * 64 + 255) / 256, 256, 0, st>>>(sc.T1, sc.ac, sc.Ah, sc.Al, n * 64);
        gemm_bf16_k<<<gg, 256, SMEM_GEMM, st>>>(sc.Ah, sc.aLoB, Wbase + W2_OFF(l), W_LO_B,
                                                b2 + bo, sc.T2, n, 256);
        colstats_k<0><<<sb, 256, 0, st>>>(sc.T2, nullptr, sc.part, n);
        finalize_k<<<1, 1024, 0, st>>>(sc.part, sb, n, bnA_g + bo, bnA_b + bo, sc.ac + 512);
        colstats_k<1><<<sb, 256, 0, st>>>(sc.T2, sc.ac + 512, sc.part, n);
        finalize_k<<<1, 1024, 0, st>>>(sc.part, sb, n, bnG_g + bo, bnG_b + bo, sc.ac + 1024);
        update_k<<<((n * 64) + 255) / 256, 256, 0, st>>>(sc.H, sc.T2, sc.ac + 512, sc.ac + 1024, n * 64);
    }
    readout_k<<<GNUM, 256, 0, st>>>(sc.H, sc.gstart, R);
}

extern "C" void kernel_launch(void* const* d_in, const int* in_sizes, int n_in,
                              void* d_out, int out_size) {
    const float* X     = (const float*)d_in[0];
    const float* X_q   = (const float*)d_in[2];
    const float* W_emb = (const float*)d_in[4];
    const float* b_emb = (const float*)d_in[5];
    const float* eps   = (const float*)d_in[6];
    const float* W1    = (const float*)d_in[7];
    const float* b1    = (const float*)d_in[8];
    const float* bn1_g = (const float*)d_in[9];
    const float* bn1_b = (const float*)d_in[10];
    const float* W2    = (const float*)d_in[11];
    const float* b2    = (const float*)d_in[12];
    const float* bnA_g = (const float*)d_in[13];
    const float* bnA_b = (const float*)d_in[14];
    const float* bnG_g = (const float*)d_in[15];
    const float* bnG_b = (const float*)d_in[16];
    const float* Wp1   = (const float*)d_in[17];
    const float* bp1   = (const float*)d_in[18];
    const float* Wp2   = (const float*)d_in[19];
    const float* bp2   = (const float*)d_in[20];
    const int* src_g   = (const int*)d_in[21];
    const int* dst_g   = (const int*)d_in[22];
    const int* gid_g   = (const int*)d_in[23];
    const int* src_q   = (const int*)d_in[24];
    const int* dst_q   = (const int*)d_in[25];
    const int* gid_q   = (const int*)d_in[26];

    int n_g = in_sizes[0] / 128;
    int e_g = in_sizes[21];
    int n_q = in_sizes[2] / 128;
    int e_q = in_sizes[24];

    Scratch sg, sq;
    __nv_bfloat16 *A2g, *A2q, *Wbase;
    cudaGetSymbolAddress((void**)&sg.H, g_H);
    cudaGetSymbolAddress((void**)&sg.T1, g_T1);
    cudaGetSymbolAddress((void**)&sg.T2, g_T2);
    cudaGetSymbolAddress((void**)&sg.part, g_part);
    cudaGetSymbolAddress((void**)&sg.ac, g_ac);
    cudaGetSymbolAddress((void**)&A2g, g_A2);
    cudaGetSymbolAddress((void**)&sg.deg, g_deg);
    cudaGetSymbolAddress((void**)&sg.rowptr, g_rowptr);
    cudaGetSymbolAddress((void**)&sg.cursor, g_cursor);
    cudaGetSymbolAddress((void**)&sg.eidx, g_eidx);
    cudaGetSymbolAddress((void**)&sg.bsum, g_bsum);
    cudaGetSymbolAddress((void**)&sg.gstart, g_gstart);
    cudaGetSymbolAddress((void**)&sq.H, q_H);
    cudaGetSymbolAddress((void**)&sq.T1, q_T1);
    cudaGetSymbolAddress((void**)&sq.T2, q_T2);
    cudaGetSymbolAddress((void**)&sq.part, q_part);
    cudaGetSymbolAddress((void**)&sq.ac, q_ac);
    cudaGetSymbolAddress((void**)&A2q, q_A2);
    cudaGetSymbolAddress((void**)&sq.deg, q_deg);
    cudaGetSymbolAddress((void**)&sq.rowptr, q_rowptr);
    cudaGetSymbolAddress((void**)&sq.cursor, q_cursor);
    cudaGetSymbolAddress((void**)&sq.eidx, q_eidx);
    cudaGetSymbolAddress((void**)&sq.bsum, q_bsum);
    cudaGetSymbolAddress((void**)&sq.gstart, q_gstart);
    cudaGetSymbolAddress((void**)&Wbase, g_W2);
    float* R;
    cudaGetSymbolAddress((void**)&R, g_R);

    sg.Ah = A2g; sg.Al = A2g + (size_t)NMAX * DH; sg.aLoB = A_LO_B_G;
    sq.Ah = A2q; sq.Al = A2q + (size_t)NQMAX * DH; sq.aLoB = A_LO_B_Q;

    cudaFuncSetAttribute(gemm_bf16_k, cudaFuncAttributeMaxDynamicSharedMemorySize, SMEM_GEMM);

    // single extra stream (R13 proven footprint)
    cudaStream_t s2;
    cudaEvent_t evFork, evJoin, evCsrG;
    cudaStreamCreateWithFlags(&s2, cudaStreamNonBlocking);
    cudaEventCreateWithFlags(&evFork, cudaEventDisableTiming);
    cudaEventCreateWithFlags(&evJoin, cudaEventDisableTiming);
    cudaEventCreateWithFlags(&evCsrG, cudaEventDisableTiming);

    wsplit_all_k<<<(WSPLIT_TOT + 255) / 256, 256>>>(W_emb, W1, W2,
                                                    Wbase, Wbase + WTOT);

    cudaEventRecord(evFork, 0);
    cudaStreamWaitEvent(s2, evFork, 0);

    // s2: g-CSR first (overlaps g-stream's split + emb GEMM), then q pipeline
    build_csr(s2, sg, n_g, src_g, dst_g, e_g, gid_g);
    cudaEventRecord(evCsrG, s2);

    // g-stream: split + emb GEMM, then wait for CSR-g, then layers
    split_k<0><<<(n_g * 32 + 255) / 256, 256>>>(X, nullptr, sg.Ah, sg.Al, n_g * 32);
    gemm_bf16_k<<<dim3((n_g + 127) / 128, 2), 256, SMEM_GEMM>>>(
        sg.Ah, sg.aLoB, Wbase + W_EMB_OFF, W_LO_B, b_emb, sg.H, n_g, 128);
    cudaStreamWaitEvent((cudaStream_t)0, evCsrG, 0);
    run_layers((cudaStream_t)0, sg, Wbase, n_g, eps,
               b1, bn1_g, bn1_b, b2, bnA_g, bnA_b, bnG_g, bnG_b, R);

    // s2: q pipeline (CSR inline on s2)
    build_csr(s2, sq, n_q, src_q, dst_q, e_q, gid_q);
    split_k<0><<<(n_q * 32 + 255) / 256, 256, 0, s2>>>(X_q, nullptr, sq.Ah, sq.Al, n_q * 32);
    gemm_bf16_k<<<dim3((n_q + 127) / 128, 2), 256, SMEM_GEMM, s2>>>(
        sq.Ah, sq.aLoB, Wbase + W_EMB_OFF, W_LO_B, b_emb, sq.H, n_q, 128);
    run_layers(s2, sq, Wbase, n_q, eps,
               b1, bn1_g, bn1_b, b2, bnA_g, bnA_b, bnG_g, bnG_b, R + GNUM * DH);

    cudaEventRecord(evJoin, s2);
    cudaStreamWaitEvent((cudaStream_t)0, evJoin, 0);

    predict_k<<<GNUM, 256>>>(R, R + GNUM * DH, Wp1, bp1, Wp2, bp2, (float*)d_out);
}

// round 15
// speedup vs baseline: 1.0765x; 1.0098x over previous
#include <cuda_runtime.h>
#include <cuda_bf16.h>
#include <cstdint>

#define DH 256
#define NMAX 50000
#define EMAX 800000
#define NQMAX 12500
#define EQMAX 200000
#define GNUM 64
#define BN_EPS 1e-5f

// ---------------- scratch (static device memory) ----------------
__device__ __align__(16) float g_H [NMAX * DH];
__device__ __align__(16) float g_T1[NMAX * DH];
__device__ __align__(16) float g_T2[NMAX * DH];
__device__ __align__(16) __nv_bfloat16 g_A2[2 * NMAX * DH];   // [hi | lo] merged
__device__ int   g_deg[NMAX + 1];
__device__ int   g_rowptr[NMAX + 1];
__device__ int   g_cursor[NMAX];
__device__ int   g_eidx[EMAX];
__device__ int   g_bsum[256];
__device__ __align__(16) float g_part[256 * 512];
__device__ __align__(16) float g_ac[3 * 512];
__device__ int   g_gstart[GNUM + 1];
__device__ __align__(16) float q_H [NQMAX * DH];
__device__ __align__(16) float q_T1[NQMAX * DH];
__device__ __align__(16) float q_T2[NQMAX * DH];
__device__ __align__(16) __nv_bfloat16 q_A2[2 * NQMAX * DH];  // [hi | lo] merged
__device__ int   q_deg[NQMAX + 1];
__device__ int   q_rowptr[NQMAX + 1];
__device__ int   q_cursor[NQMAX];
__device__ int   q_eidx[EQMAX];
__device__ int   q_bsum[256];
__device__ __align__(16) float q_part[256 * 512];
__device__ __align__(16) float q_ac[3 * 512];
__device__ int   q_gstart[GNUM + 1];
__device__ __align__(16) float g_R[2 * GNUM * DH];

#define W_EMB_OFF 0
#define W1_OFF(l) (32768 + (l) * 65536)
#define W2_OFF(l) (32768 + 262144 + (l) * 65536)
#define WTOT      (32768 + 524288)
__device__ __align__(16) __nv_bfloat16 g_W2[2 * WTOT];        // [hi | lo] merged

#define A_LO_B_G (NMAX * DH * 2)
#define A_LO_B_Q (NQMAX * DH * 2)
#define W_LO_B   (WTOT * 2)

// ---------------- helpers ----------------
__device__ __forceinline__ uint32_t smem_u32(const void* p) {
    return (uint32_t)__cvta_generic_to_shared(p);
}
__device__ __forceinline__ void cp16(uint32_t dst, const void* src) {
    asm volatile("cp.async.cg.shared.global [%0], [%1], 16;" :: "r"(dst), "l"(src) : "memory");
}
#define CP_COMMIT() asm volatile("cp.async.commit_group;" ::: "memory")
#define CP_WAIT1()  asm volatile("cp.async.wait_group 1;" ::: "memory")
#define CP_WAIT0()  asm volatile("cp.async.wait_group 0;" ::: "memory")

__device__ __forceinline__ void mma16816(float* d, const uint32_t* a, uint32_t b0, uint32_t b1) {
    asm volatile(
        "mma.sync.aligned.m16n8k16.row.col.f32.bf16.bf16.f32 "
        "{%0,%1,%2,%3}, {%4,%5,%6,%7}, {%8,%9}, {%0,%1,%2,%3};"
        : "+f"(d[0]), "+f"(d[1]), "+f"(d[2]), "+f"(d[3])
        : "r"(a[0]), "r"(a[1]), "r"(a[2]), "r"(a[3]), "r"(b0), "r"(b1));
}
__device__ __forceinline__ void ldsm4(uint32_t& r0, uint32_t& r1, uint32_t& r2, uint32_t& r3,
                                      uint32_t addr) {
    asm volatile("ldmatrix.sync.aligned.m8n8.x4.shared.b16 {%0,%1,%2,%3}, [%4];"
                 : "=r"(r0), "=r"(r1), "=r"(r2), "=r"(r3) : "r"(addr));
}

// 64B-pitch conflict-free tile swizzle (verified R10/R11)
__device__ __forceinline__ uint32_t swz(uint32_t r, uint32_t q) {
    return (r >> 1) * 128 + (((r & 1) * 4 + (q ^ ((r >> 1) & 3))) << 4);
}

__device__ __forceinline__ uint2 split4(float4 v) {
    __nv_bfloat16 hx = __float2bfloat16(v.x), hy = __float2bfloat16(v.y);
    __nv_bfloat16 hz = __float2bfloat16(v.z), hw = __float2bfloat16(v.w);
    __nv_bfloat162 p0 = __halves2bfloat162(hx, hy);
    __nv_bfloat162 p1 = __halves2bfloat162(hz, hw);
    return make_uint2(*(uint32_t*)&p0, *(uint32_t*)&p1);
}
__device__ __forceinline__ uint2 split4lo(float4 v, uint2 hi) {
    __nv_bfloat162 h0 = *(__nv_bfloat162*)&hi.x;
    __nv_bfloat162 h1 = *(__nv_bfloat162*)&hi.y;
    __nv_bfloat16 lx = __float2bfloat16(v.x - __bfloat162float(__low2bfloat16(h0)));
    __nv_bfloat16 ly = __float2bfloat16(v.y - __bfloat162float(__high2bfloat16(h0)));
    __nv_bfloat16 lz = __float2bfloat16(v.z - __bfloat162float(__low2bfloat16(h1)));
    __nv_bfloat16 lw = __float2bfloat16(v.w - __bfloat162float(__high2bfloat16(h1)));
    __nv_bfloat162 p0 = __halves2bfloat162(lx, ly);
    __nv_bfloat162 p1 = __halves2bfloat162(lz, lw);
    return make_uint2(*(uint32_t*)&p0, *(uint32_t*)&p1);
}

// ---------------- small utility kernels ----------------
__global__ __launch_bounds__(256) void zero_int_k(int* p, int n) {
    int i = blockIdx.x * 256 + threadIdx.x;
    if (i < n) p[i] = 0;
}
__global__ __launch_bounds__(256) void hist_k(const int* __restrict__ dst, int ne, int* deg) {
    int i = blockIdx.x * 256 + threadIdx.x;
    if (i < ne) atomicAdd(&deg[dst[i]], 1);
}
// hierarchical scan: per-block sums -> tiny scan -> expand (contention-robust)
__global__ __launch_bounds__(256) void blocksum_k(const int* __restrict__ deg,
                                                  int* __restrict__ bsum, int n) {
    __shared__ int sh[256];
    int t = threadIdx.x;
    int i = blockIdx.x * 256 + t;
    sh[t] = (i < n) ? deg[i] : 0;
    __syncthreads();
    for (int s = 128; s > 0; s >>= 1) {
        if (t < s) sh[t] += sh[t + s];
        __syncthreads();
    }
    if (t == 0) bsum[blockIdx.x] = sh[0];
}
__global__ void scanb_k(int* __restrict__ bsum, int nb) {
    __shared__ int sh[256];
    int t = threadIdx.x;
    int v = (t < nb) ? bsum[t] : 0;
    sh[t] = v;
    __syncthreads();
    for (int off = 1; off < 256; off <<= 1) {
        int u = (t >= off) ? sh[t - off] : 0;
        __syncthreads();
        sh[t] += u;
        __syncthreads();
    }
    if (t < nb) bsum[t] = sh[t] - v;   // exclusive prefix of block sums
}
__global__ __launch_bounds__(256) void expand_k(const int* __restrict__ deg,
                                                const int* __restrict__ bsumx,
                                                int* __restrict__ rowptr,
                                                int* __restrict__ cursor, int n) {
    __shared__ int sh[256];
    int t = threadIdx.x;
    int i = blockIdx.x * 256 + t;
    int v = (i < n) ? deg[i] : 0;
    sh[t] = v;
    __syncthreads();
    for (int off = 1; off < 256; off <<= 1) {
        int u = (t >= off) ? sh[t - off] : 0;
        __syncthreads();
        sh[t] += u;
        __syncthreads();
    }
    if (i < n) {
        int incl = sh[t] + bsumx[blockIdx.x];
        cursor[i] = incl - v;
        rowptr[i + 1] = incl;
    }
    if (i == 0) rowptr[0] = 0;
}
__global__ __launch_bounds__(256) void fill_k(const int* __restrict__ src, const int* __restrict__ dst,
                                              int ne, int* cursor, int* __restrict__ eidx) {
    int i = blockIdx.x * 256 + threadIdx.x;
    if (i < ne) {
        int p = atomicAdd(&cursor[dst[i]], 1);
        eidx[p] = src[i];
    }
}
__global__ void bounds_k(const int* __restrict__ gid, int n, int* __restrict__ gs) {
    int g = threadIdx.x;
    if (g > GNUM) return;
    int lo = 0, hi = n;
    while (lo < hi) {
        int mid = (lo + hi) >> 1;
        if (gid[mid] < g) lo = mid + 1; else hi = mid;
    }
    gs[g] = lo;
}

#define WSPLIT_TOT 557056
__global__ __launch_bounds__(256) void wsplit_all_k(const float* __restrict__ W_emb,
                                                    const float* __restrict__ W1,
                                                    const float* __restrict__ W2,
                                                    __nv_bfloat16* __restrict__ Wh,
                                                    __nv_bfloat16* __restrict__ Wl) {
    int i = blockIdx.x * 256 + threadIdx.x;
    if (i >= WSPLIT_TOT) return;
    const float* W;
    int idx, K;
    size_t base;
    if (i < 32768) {
        W = W_emb; idx = i; K = 128; base = W_EMB_OFF;
    } else if (i < 32768 + 262144) {
        int j = i - 32768;
        int l = j >> 16;
        W = W1 + (size_t)l * 65536; idx = j & 65535; K = 256; base = W1_OFF(l);
    } else {
        int j = i - 32768 - 262144;
        int l = j >> 16;
        W = W2 + (size_t)l * 65536; idx = j & 65535; K = 256; base = W2_OFF(l);
    }
    int k = idx >> 8, n = idx & 255;
    float x = W[idx];
    __nv_bfloat16 h = __float2bfloat16(x);
    float r = x - __bfloat162float(h);
    Wh[base + (size_t)n * K + k] = h;
    Wl[base + (size_t)n * K + k] = __float2bfloat16(r);
}

// ---------------- activation split (FOLD=1: relu(a*x+c) first) ----------------
template <int FOLD>
__global__ __launch_bounds__(256) void split_k(const float* __restrict__ T,
                                               const float* __restrict__ ac,
                                               __nv_bfloat16* __restrict__ Ah,
                                               __nv_bfloat16* __restrict__ Al, int n4) {
    int i = blockIdx.x * 256 + threadIdx.x;
    if (i >= n4) return;
    float4 v = ((const float4*)T)[i];
    if (FOLD) {
        int cb = (i * 4) & 255;
        float4 a = *(const float4*)&ac[cb];
        float4 c = *(const float4*)&ac[256 + cb];
        v.x = fmaxf(fmaf(a.x, v.x, c.x), 0.f);
        v.y = fmaxf(fmaf(a.y, v.y, c.y), 0.f);
        v.z = fmaxf(fmaf(a.z, v.z, c.z), 0.f);
        v.w = fmaxf(fmaf(a.w, v.w, c.w), 0.f);
    }
    uint2 hi = split4(v);
    uint2 lo = split4lo(v, hi);
    *(uint2*)(Ah + (size_t)i * 4) = hi;
    *(uint2*)(Al + (size_t)i * 4) = lo;
}

// ---------------- GIN aggregation (4-edge unrolled) -> split bf16 output ----------------
__global__ void agg_k(const float* __restrict__ H,
                      __nv_bfloat16* __restrict__ Ah, __nv_bfloat16* __restrict__ Al,
                      const int* __restrict__ rowptr, const int* __restrict__ eidx,
                      const float* __restrict__ eps, int l, int n) {
    int node = blockIdx.x * 8 + threadIdx.y;
    if (node >= n) return;
    int lane = threadIdx.x;
    const float4* h4 = (const float4*)(H + (size_t)node * DH);
    float ep = 1.0f + eps[l];
    float4 a0 = h4[lane];
    float4 a1 = h4[lane + 32];
    a0.x *= ep; a0.y *= ep; a0.z *= ep; a0.w *= ep;
    a1.x *= ep; a1.y *= ep; a1.z *= ep; a1.w *= ep;
    int beg = rowptr[node], end = rowptr[node + 1];
    int j = beg;
    for (; j + 3 < end; j += 4) {
        const float4* s0 = (const float4*)(H + (size_t)eidx[j] * DH);
        const float4* s1 = (const float4*)(H + (size_t)eidx[j + 1] * DH);
        const float4* s2 = (const float4*)(H + (size_t)eidx[j + 2] * DH);
        const float4* s3 = (const float4*)(H + (size_t)eidx[j + 3] * DH);
        float4 p00 = s0[lane], p01 = s0[lane + 32];
        float4 p10 = s1[lane], p11 = s1[lane + 32];
        float4 p20 = s2[lane], p21 = s2[lane + 32];
        float4 p30 = s3[lane], p31 = s3[lane + 32];
        a0.x += (p00.x + p10.x) + (p20.x + p30.x);
        a0.y += (p00.y + p10.y) + (p20.y + p30.y);
        a0.z += (p00.z + p10.z) + (p20.z + p30.z);
        a0.w += (p00.w + p10.w) + (p20.w + p30.w);
        a1.x += (p01.x + p11.x) + (p21.x + p31.x);
        a1.y += (p01.y + p11.y) + (p21.y + p31.y);
        a1.z += (p01.z + p11.z) + (p21.z + p31.z);
        a1.w += (p01.w + p11.w) + (p21.w + p31.w);
    }
    for (; j < end; j++) {
        const float4* sA = (const float4*)(H + (size_t)eidx[j] * DH);
        float4 pa0 = sA[lane], pa1 = sA[lane + 32];
        a0.x += pa0.x; a0.y += pa0.y; a0.z += pa0.z; a0.w += pa0.w;
        a1.x += pa1.x; a1.y += pa1.y; a1.z += pa1.z; a1.w += pa1.w;
    }
    uint2 h0 = split4(a0), h1 = split4(a1);
    uint2 l0 = split4lo(a0, h0), l1 = split4lo(a1, h1);
    size_t base = (size_t)node * DH + lane * 4;
    *(uint2*)(Ah + base) = h0;
    *(uint2*)(Ah + base + 128) = h1;
    *(uint2*)(Al + base) = l0;
    *(uint2*)(Al + base + 128) = l1;
}

// ---------------- all-bf16 mma.sync GEMM: 3-stage pipeline, merged hi/lo buffers ----------------
#define TSZ 8192
#define STG 32768
#define OFF_BIAS 98304
#define SMEM_GEMM (OFF_BIAS + 512)

__global__ __launch_bounds__(256, 2) void gemm_bf16_k(
    const __nv_bfloat16* __restrict__ A, uint32_t aLoB,
    const __nv_bfloat16* __restrict__ B, uint32_t bLoB,
    const float* __restrict__ bias, float* __restrict__ C, int M, int K)
{
    extern __shared__ char smem[];
    uint32_t sb = smem_u32(smem);
    int tid = threadIdx.x;
    int wid = tid >> 5, lane = tid & 31;
    int wm = wid >> 1, wn = wid & 1;
    int g = lane >> 2, tq = lane & 3;
    int m0 = blockIdx.x * 128, n0 = blockIdx.y * 128;
    int NC = K >> 5;

    if (tid < 32) ((float4*)(smem + OFF_BIAS))[tid] = ((const float4*)(bias + n0))[tid];

    int r1 = tid >> 2, q1 = tid & 3;
    uint32_t sw1 = swz((uint32_t)r1, (uint32_t)q1);
    int ar0 = min(m0 + r1, M - 1);
    int ar1 = min(m0 + r1 + 64, M - 1);
    const char* ag0 = (const char*)(A + (size_t)ar0 * K);
    const char* ag1 = (const char*)(A + (size_t)ar1 * K);
    const char* bg0 = (const char*)(B + (size_t)(n0 + r1) * K);
    const char* bg1 = (const char*)(B + (size_t)(n0 + r1 + 64) * K);

    auto issue = [&](int kc) {
        uint32_t bs = sb + (uint32_t)(kc % 3) * STG;
        int go = kc * 64 + q1 * 16;
        cp16(bs + sw1,                  ag0 + go);
        cp16(bs + sw1 + 4096,           ag1 + go);
        cp16(bs + TSZ + sw1,            ag0 + go + aLoB);
        cp16(bs + TSZ + sw1 + 4096,     ag1 + go + aLoB);
        cp16(bs + 2 * TSZ + sw1,        bg0 + go);
        cp16(bs + 2 * TSZ + sw1 + 4096, bg1 + go);
        cp16(bs + 3 * TSZ + sw1,        bg0 + go + bLoB);
        cp16(bs + 3 * TSZ + sw1 + 4096, bg1 + go + bLoB);
        CP_COMMIT();
    };

    uint32_t rA = (uint32_t)(wm * 32 + (lane & 15));
    uint32_t qA = (uint32_t)((lane >> 4) & 1);
    uint32_t aA0 = swz(rA, qA);
    uint32_t aA1 = swz(rA, qA + 2);
    uint32_t rB = (uint32_t)(wn * 64 + (lane & 7) + ((lane >> 4) & 1) * 8);
    uint32_t qB = (uint32_t)((lane >> 3) & 1);
    uint32_t bA0 = swz(rB, qB);
    uint32_t bA1 = swz(rB, qB + 2);

    float acc[2][8][4];
#pragma unroll
    for (int mt = 0; mt < 2; mt++)
#pragma unroll
        for (int nn = 0; nn < 8; nn++)
#pragma unroll
            for (int r = 0; r < 4; r++) acc[mt][nn][r] = 0.0f;

    issue(0);
    issue(1);

    for (int kc = 0; kc < NC; kc++) {
        if (kc + 1 < NC) { CP_WAIT1(); } else { CP_WAIT0(); }
        __syncthreads();
        if (kc + 2 < NC) issue(kc + 2);

        uint32_t st = sb + (uint32_t)(kc % 3) * STG;
#pragma unroll
        for (int ks = 0; ks < 2; ks++) {
            uint32_t aoff = st + (ks ? aA1 : aA0);
            uint32_t boff = st + 2 * TSZ + (ks ? bA1 : bA0);
            uint32_t ah[2][4], al[2][4];
#pragma unroll
            for (int mt = 0; mt < 2; mt++) {
                ldsm4(ah[mt][0], ah[mt][1], ah[mt][2], ah[mt][3], aoff + mt * 1024);
                ldsm4(al[mt][0], al[mt][1], al[mt][2], al[mt][3], aoff + TSZ + mt * 1024);
            }
#pragma unroll
            for (int np = 0; np < 4; np++) {
                uint32_t bb = boff + np * 1024;
                uint32_t bh0, bh1, bh2, bh3, bl0, bl1, bl2, bl3;
                ldsm4(bh0, bh1, bh2, bh3, bb);
                ldsm4(bl0, bl1, bl2, bl3, bb + TSZ);
                int nn = np * 2;
                // grouped by product: per-accumulator order unchanged (bh, bl, al*bh)
                // but same-accumulator dependency distance stretched 2 -> 4
                mma16816(acc[0][nn],     ah[0], bh0, bh1);
                mma16816(acc[1][nn],     ah[1], bh0, bh1);
                mma16816(acc[0][nn + 1], ah[0], bh2, bh3);
                mma16816(acc[1][nn + 1], ah[1], bh2, bh3);
                mma16816(acc[0][nn],     ah[0], bl0, bl1);
                mma16816(acc[1][nn],     ah[1], bl0, bl1);
                mma16816(acc[0][nn + 1], ah[0], bl2, bl3);
                mma16816(acc[1][nn + 1], ah[1], bl2, bl3);
                mma16816(acc[0][nn],     al[0], bh0, bh1);
                mma16816(acc[1][nn],     al[1], bh0, bh1);
                mma16816(acc[0][nn + 1], al[0], bh2, bh3);
                mma16816(acc[1][nn + 1], al[1], bh2, bh3);
            }
        }
    }

    const float* biasS = (const float*)(smem + OFF_BIAS);
#pragma unroll
    for (int mt = 0; mt < 2; mt++) {
        int row = m0 + wm * 32 + mt * 16 + g;
#pragma unroll
        for (int nn = 0; nn < 8; nn++) {
            int colr = wn * 64 + nn * 8 + 2 * tq;
            float b0 = biasS[colr], b1 = biasS[colr + 1];
            int col = n0 + colr;
            if (row < M)
                *(float2*)&C[(size_t)row * 256 + col] =
                    make_float2(acc[mt][nn][0] + b0, acc[mt][nn][1] + b1);
            if (row + 8 < M)
                *(float2*)&C[(size_t)(row + 8) * 256 + col] =
                    make_float2(acc[mt][nn][2] + b0, acc[mt][nn][3] + b1);
        }
    }
}

// ---------------- column stats (4 independent row streams) ----------------
template <int TRANS>
__global__ void colstats_k(const float* __restrict__ T, const float* __restrict__ tac,
                           float* __restrict__ part, int M) {
    int c = threadIdx.x;
    int r0 = blockIdx.x * 256;
    float a = 0.f, b = 0.f;
    if (TRANS) { a = tac[c]; b = tac[256 + c]; }
    float s0 = 0.f, s1 = 0.f, s2 = 0.f, s3 = 0.f;
    float q0 = 0.f, q1 = 0.f, q2 = 0.f, q3 = 0.f;
    const float* base = T + c;
#pragma unroll 4
    for (int j = 0; j < 64; j++) {
        int r = r0 + j;
        float x0 = (r < M)       ? base[(size_t)r * DH]         : 0.f;
        float x1 = (r + 64 < M)  ? base[(size_t)(r + 64) * DH]  : 0.f;
        float x2 = (r + 128 < M) ? base[(size_t)(r + 128) * DH] : 0.f;
        float x3 = (r + 192 < M) ? base[(size_t)(r + 192) * DH] : 0.f;
        if (TRANS) {
            x0 = (r < M)       ? fmaxf(fmaf(a, x0, b), 0.f) : 0.f;
            x1 = (r + 64 < M)  ? fmaxf(fmaf(a, x1, b), 0.f) : 0.f;
            x2 = (r + 128 < M) ? fmaxf(fmaf(a, x2, b), 0.f) : 0.f;
            x3 = (r + 192 < M) ? fmaxf(fmaf(a, x3, b), 0.f) : 0.f;
        }
        s0 += x0; q0 += x0 * x0;
        s1 += x1; q1 += x1 * x1;
        s2 += x2; q2 += x2 * x2;
        s3 += x3; q3 += x3 * x3;
    }
    part[blockIdx.x * 512 + c] = (s0 + s1) + (s2 + s3);
    part[blockIdx.x * 512 + 256 + c] = (q0 + q1) + (q2 + q3);
}

__global__ void finalize_k(const float* __restrict__ part, int nb, int n,
                           const float* __restrict__ gamma, const float* __restrict__ beta,
                           float* __restrict__ ac) {
    __shared__ float sh[4][512];
    int c = threadIdx.x & 255;
    int seg = threadIdx.x >> 8;
    int b0 = (nb * seg) >> 2, b1 = (nb * (seg + 1)) >> 2;
    float s = 0.f, ss = 0.f;
    for (int b = b0; b < b1; b++) {
        s += part[b * 512 + c];
        ss += part[b * 512 + 256 + c];
    }
    sh[seg][c] = s;
    sh[seg][256 + c] = ss;
    __syncthreads();
    if (seg == 0) {
        float ts = (sh[0][c] + sh[1][c]) + (sh[2][c] + sh[3][c]);
        float tss = (sh[0][256 + c] + sh[1][256 + c]) + (sh[2][256 + c] + sh[3][256 + c]);
        float inv = 1.0f / (float)n;
        float m = ts * inv;
        float v = tss * inv - m * m;
        float a = gamma[c] * rsqrtf(v + BN_EPS);
        ac[c] = a;
        ac[256 + c] = beta[c] - a * m;
    }
}

__global__ __launch_bounds__(256) void update_k(float* __restrict__ H, const float* __restrict__ T2,
                                                const float* __restrict__ acA, const float* __restrict__ acG,
                                                int n4) {
    int i = blockIdx.x * 256 + threadIdx.x;
    if (i >= n4) return;
    int cb = (i * 4) & 255;
    float4 t  = ((const float4*)T2)[i];
    float4 aA = *(const float4*)&acA[cb];
    float4 cA = *(const float4*)&acA[256 + cb];
    float4 aG = *(const float4*)&acG[cb];
    float4 cG = *(const float4*)&acG[256 + cb];
    float4 h  = ((float4*)H)[i];
    h.x += fmaxf(aG.x * fmaxf(aA.x * t.x + cA.x, 0.f) + cG.x, 0.f);
    h.y += fmaxf(aG.y * fmaxf(aA.y * t.y + cA.y, 0.f) + cG.y, 0.f);
    h.z += fmaxf(aG.z * fmaxf(aA.z * t.z + cA.z, 0.f) + cG.z, 0.f);
    h.w += fmaxf(aG.w * fmaxf(aA.w * t.w + cA.w, 0.f) + cG.w, 0.f);
    ((float4*)H)[i] = h;
}

__global__ void readout_k(const float* __restrict__ H, const int* __restrict__ gs,
                          float* __restrict__ R) {
    int g = blockIdx.x;
    int c = threadIdx.x;
    int beg = gs[g], end = gs[g + 1];
    float s = 0.f;
    for (int i = beg; i < end; i++) s += H[(size_t)i * DH + c];
    R[g * DH + c] = s;
}

__global__ void predict_k(const float* __restrict__ Rg, const float* __restrict__ Rq,
                          const float* __restrict__ Wp1, const float* __restrict__ bp1,
                          const float* __restrict__ Wp2, const float* __restrict__ bp2,
                          float* __restrict__ out) {
    int g = blockIdx.x;
    int t = threadIdx.x;
    __shared__ float d[256];
    __shared__ float red[256];
    d[t] = fabsf(Rg[g * DH + t] - Rq[g * DH + t]);
    __syncthreads();
    float acc = bp1[t];
    for (int k = 0; k < 256; k++) acc += d[k] * Wp1[k * 256 + t];
    acc = fmaxf(acc, 0.f);
    red[t] = acc * Wp2[t];
    __syncthreads();
    for (int s = 128; s > 0; s >>= 1) {
        if (t < s) red[t] += red[t + s];
        __syncthreads();
    }
    if (t == 0) out[g] = red[0] + bp2[0];
}

// ---------------- host orchestration ----------------
struct Scratch {
    float *H, *T1, *T2, *part, *ac;
    __nv_bfloat16 *Ah, *Al;
    uint32_t aLoB;
    int *deg, *rowptr, *cursor, *eidx, *bsum, *gstart;
};

static void build_csr(cudaStream_t st, const Scratch& sc, int n,
                      const int* src, const int* dst, int ne, const int* gid) {
    int nb = (n + 255) / 256;
    zero_int_k<<<(n + 256) / 256, 256, 0, st>>>(sc.deg, n + 1);
    hist_k<<<(ne + 255) / 256, 256, 0, st>>>(dst, ne, sc.deg);
    blocksum_k<<<nb, 256, 0, st>>>(sc.deg, sc.bsum, n);
    scanb_k<<<1, 256, 0, st>>>(sc.bsum, nb);
    expand_k<<<nb, 256, 0, st>>>(sc.deg, sc.bsum, sc.rowptr, sc.cursor, n);
    fill_k<<<(ne + 255) / 256, 256, 0, st>>>(src, dst, ne, sc.cursor, sc.eidx);
    bounds_k<<<1, GNUM + 1, 0, st>>>(gid, n, sc.gstart);
}

static void run_layers(cudaStream_t st, const Scratch& sc, const __nv_bfloat16* Wbase,
                       int n, const float* eps,
                       const float* b1, const float* bn1_g, const float* bn1_b,
                       const float* b2, const float* bnA_g, const float* bnA_b,
                       const float* bnG_g, const float* bnG_b,
                       float* R) {
    int gx = (n + 127) / 128;
    dim3 gg(gx, 2);
    int sb = (n + 255) / 256;
    for (int l = 0; l < 4; l++) {
        int bo = l * 256;
        agg_k<<<(n + 7) / 8, dim3(32, 8), 0, st>>>(sc.H, sc.Ah, sc.Al, sc.rowptr, sc.eidx, eps, l, n);
        gemm_bf16_k<<<gg, 256, SMEM_GEMM, st>>>(sc.Ah, sc.aLoB, Wbase + W1_OFF(l), W_LO_B,
                                                b1 + bo, sc.T1, n, 256);
        colstats_k<0><<<sb, 256, 0, st>>>(sc.T1, nullptr, sc.part, n);
        finalize_k<<<1, 1024, 0, st>>>(sc.part, sb, n, bn1_g + bo, bn1_b + bo, sc.ac);
        split_k<1><<<(n * 64 + 255) / 256, 256, 0, st>>>(sc.T1, sc.ac, sc.Ah, sc.Al, n * 64);
        gemm_bf16_k<<<gg, 256, SMEM_GEMM, st>>>(sc.Ah, sc.aLoB, Wbase + W2_OFF(l), W_LO_B,
                                                b2 + bo, sc.T2, n, 256);
        colstats_k<0><<<sb, 256, 0, st>>>(sc.T2, nullptr, sc.part, n);
        finalize_k<<<1, 1024, 0, st>>>(sc.part, sb, n, bnA_g + bo, bnA_b + bo, sc.ac + 512);
        colstats_k<1><<<sb, 256, 0, st>>>(sc.T2, sc.ac + 512, sc.part, n);
        finalize_k<<<1, 1024, 0, st>>>(sc.part, sb, n, bnG_g + bo, bnG_b + bo, sc.ac + 1024);
        update_k<<<((n * 64) + 255) / 256, 256, 0, st>>>(sc.H, sc.T2, sc.ac + 512, sc.ac + 1024, n * 64);
    }
    readout_k<<<GNUM, 256, 0, st>>>(sc.H, sc.gstart, R);
}

extern "C" void kernel_launch(void* const* d_in, const int* in_sizes, int n_in,
                              void* d_out, int out_size) {
    const float* X     = (const float*)d_in[0];
    const float* X_q   = (const float*)d_in[2];
    const float* W_emb = (const float*)d_in[4];
    const float* b_emb = (const float*)d_in[5];
    const float* eps   = (const float*)d_in[6];
    const float* W1    = (const float*)d_in[7];
    const float* b1    = (const float*)d_in[8];
    const float* bn1_g = (const float*)d_in[9];
    const float* bn1_b = (const float*)d_in[10];
    const float* W2    = (const float*)d_in[11];
    const float* b2    = (const float*)d_in[12];
    const float* bnA_g = (const float*)d_in[13];
    const float* bnA_b = (const float*)d_in[14];
    const float* bnG_g = (const float*)d_in[15];
    const float* bnG_b = (const float*)d_in[16];
    const float* Wp1   = (const float*)d_in[17];
    const float* bp1   = (const float*)d_in[18];
    const float* Wp2   = (const float*)d_in[19];
    const float* bp2   = (const float*)d_in[20];
    const int* src_g   = (const int*)d_in[21];
    const int* dst_g   = (const int*)d_in[22];
    const int* gid_g   = (const int*)d_in[23];
    const int* src_q   = (const int*)d_in[24];
    const int* dst_q   = (const int*)d_in[25];
    const int* gid_q   = (const int*)d_in[26];

    int n_g = in_sizes[0] / 128;
    int e_g = in_sizes[21];
    int n_q = in_sizes[2] / 128;
    int e_q = in_sizes[24];

    Scratch sg, sq;
    __nv_bfloat16 *A2g, *A2q, *Wbase;
    cudaGetSymbolAddress((void**)&sg.H, g_H);
    cudaGetSymbolAddress((void**)&sg.T1, g_T1);
    cudaGetSymbolAddress((void**)&sg.T2, g_T2);
    cudaGetSymbolAddress((void**)&sg.part, g_part);
    cudaGetSymbolAddress((void**)&sg.ac, g_ac);
    cudaGetSymbolAddress((void**)&A2g, g_A2);
    cudaGetSymbolAddress((void**)&sg.deg, g_deg);
    cudaGetSymbolAddress((void**)&sg.rowptr, g_rowptr);
    cudaGetSymbolAddress((void**)&sg.cursor, g_cursor);
    cudaGetSymbolAddress((void**)&sg.eidx, g_eidx);
    cudaGetSymbolAddress((void**)&sg.bsum, g_bsum);
    cudaGetSymbolAddress((void**)&sg.gstart, g_gstart);
    cudaGetSymbolAddress((void**)&sq.H, q_H);
    cudaGetSymbolAddress((void**)&sq.T1, q_T1);
    cudaGetSymbolAddress((void**)&sq.T2, q_T2);
    cudaGetSymbolAddress((void**)&sq.part, q_part);
    cudaGetSymbolAddress((void**)&sq.ac, q_ac);
    cudaGetSymbolAddress((void**)&A2q, q_A2);
    cudaGetSymbolAddress((void**)&sq.deg, q_deg);
    cudaGetSymbolAddress((void**)&sq.rowptr, q_rowptr);
    cudaGetSymbolAddress((void**)&sq.cursor, q_cursor);
    cudaGetSymbolAddress((void**)&sq.eidx, q_eidx);
    cudaGetSymbolAddress((void**)&sq.bsum, q_bsum);
    cudaGetSymbolAddress((void**)&sq.gstart, q_gstart);
    cudaGetSymbolAddress((void**)&Wbase, g_W2);
    float* R;
    cudaGetSymbolAddress((void**)&R, g_R);

    sg.Ah = A2g; sg.Al = A2g + (size_t)NMAX * DH; sg.aLoB = A_LO_B_G;
    sq.Ah = A2q; sq.Al = A2q + (size_t)NQMAX * DH; sq.aLoB = A_LO_B_Q;

    cudaFuncSetAttribute(gemm_bf16_k, cudaFuncAttributeMaxDynamicSharedMemorySize, SMEM_GEMM);

    // single extra stream (R13/R14 proven footprint)
    cudaStream_t s2;
    cudaEvent_t evFork, evJoin, evCsrG;
    cudaStreamCreateWithFlags(&s2, cudaStreamNonBlocking);
    cudaEventCreateWithFlags(&evFork, cudaEventDisableTiming);
    cudaEventCreateWithFlags(&evJoin, cudaEventDisableTiming);
    cudaEventCreateWithFlags(&evCsrG, cudaEventDisableTiming);

    wsplit_all_k<<<(WSPLIT_TOT + 255) / 256, 256>>>(W_emb, W1, W2,
                                                    Wbase, Wbase + WTOT);

    cudaEventRecord(evFork, 0);
    cudaStreamWaitEvent(s2, evFork, 0);

    // s2: g-CSR first (overlaps g-stream's split + emb GEMM), then q pipeline
    build_csr(s2, sg, n_g, src_g, dst_g, e_g, gid_g);
    cudaEventRecord(evCsrG, s2);

    // g-stream: split + emb GEMM, then wait for CSR-g, then layers
    split_k<0><<<(n_g * 32 + 255) / 256, 256>>>(X, nullptr, sg.Ah, sg.Al, n_g * 32);
    gemm_bf16_k<<<dim3((n_g + 127) / 128, 2), 256, SMEM_GEMM>>>(
        sg.Ah, sg.aLoB, Wbase + W_EMB_OFF, W_LO_B, b_emb, sg.H, n_g, 128);
    cudaStreamWaitEvent((cudaStream_t)0, evCsrG, 0);
    run_layers((cudaStream_t)0, sg, Wbase, n_g, eps,
               b1, bn1_g, bn1_b, b2, bnA_g, bnA_b, bnG_g, bnG_b, R);

    // s2: q pipeline (CSR inline on s2)
    build_csr(s2, sq, n_q, src_q, dst_q, e_q, gid_q);
    split_k<0><<<(n_q * 32 + 255) / 256, 256, 0, s2>>>(X_q, nullptr, sq.Ah, sq.Al, n_q * 32);
    gemm_bf16_k<<<dim3((n_q + 127) / 128, 2), 256, SMEM_GEMM, s2>>>(
        sq.Ah, sq.aLoB, Wbase + W_EMB_OFF, W_LO_B, b_emb, sq.H, n_q, 128);
    run_layers(s2, sq, Wbase, n_q, eps,
               b1, bn1_g, bn1_b, b2, bnA_g, bnA_b, bnG_g, bnG_b, R + GNUM * DH);

    cudaEventRecord(evJoin, s2);
    cudaStreamWaitEvent((cudaStream_t)0, evJoin, 0);

    predict_k<<<GNUM, 256>>>(R, R + GNUM * DH, Wp1, bp1, Wp2, bp2, (float*)d_out);
}

// round 16
// speedup vs baseline: 1.1038x; 1.0253x over previous
#include <cuda_runtime.h>
#include <cuda_bf16.h>
#include <cstdint>

#define DH 256
#define NMAX 50000
#define EMAX 800000
#define NQMAX 12500
#define EQMAX 200000
#define GNUM 64
#define BN_EPS 1e-5f

// ---------------- scratch (static device memory) ----------------
__device__ __align__(16) float g_H [NMAX * DH];
__device__ __align__(16) float g_T1[NMAX * DH];
__device__ __align__(16) float g_T2[NMAX * DH];
__device__ __align__(16) __nv_bfloat16 g_A2[2 * NMAX * DH];   // [hi | lo] merged
__device__ int   g_deg[NMAX + 1];
__device__ int   g_rowptr[NMAX + 1];
__device__ int   g_cursor[NMAX];
__device__ int   g_eidx[EMAX];
__device__ int   g_bsum[256];
__device__ __align__(16) float g_part[256 * 512];
__device__ __align__(16) float g_ac[3 * 512];
__device__ int   g_gstart[GNUM + 1];
__device__ __align__(16) float q_H [NQMAX * DH];
__device__ __align__(16) float q_T1[NQMAX * DH];
__device__ __align__(16) float q_T2[NQMAX * DH];
__device__ __align__(16) __nv_bfloat16 q_A2[2 * NQMAX * DH];  // [hi | lo] merged
__device__ int   q_deg[NQMAX + 1];
__device__ int   q_rowptr[NQMAX + 1];
__device__ int   q_cursor[NQMAX];
__device__ int   q_eidx[EQMAX];
__device__ int   q_bsum[256];
__device__ __align__(16) float q_part[256 * 512];
__device__ __align__(16) float q_ac[3 * 512];
__device__ int   q_gstart[GNUM + 1];
__device__ __align__(16) float g_R[2 * GNUM * DH];

#define W_EMB_OFF 0
#define W1_OFF(l) (32768 + (l) * 65536)
#define W2_OFF(l) (32768 + 262144 + (l) * 65536)
#define WTOT      (32768 + 524288)
__device__ __align__(16) __nv_bfloat16 g_W2[2 * WTOT];        // [hi | lo] merged

#define A_LO_B_G (NMAX * DH * 2)
#define A_LO_B_Q (NQMAX * DH * 2)
#define W_LO_B   (WTOT * 2)

// ---------------- helpers ----------------
__device__ __forceinline__ uint32_t smem_u32(const void* p) {
    return (uint32_t)__cvta_generic_to_shared(p);
}
__device__ __forceinline__ void cp16(uint32_t dst, const void* src) {
    asm volatile("cp.async.cg.shared.global [%0], [%1], 16;" :: "r"(dst), "l"(src) : "memory");
}
#define CP_COMMIT() asm volatile("cp.async.commit_group;" ::: "memory")
#define CP_WAIT1()  asm volatile("cp.async.wait_group 1;" ::: "memory")
#define CP_WAIT0()  asm volatile("cp.async.wait_group 0;" ::: "memory")

__device__ __forceinline__ void mma16816(float* d, const uint32_t* a, uint32_t b0, uint32_t b1) {
    asm volatile(
        "mma.sync.aligned.m16n8k16.row.col.f32.bf16.bf16.f32 "
        "{%0,%1,%2,%3}, {%4,%5,%6,%7}, {%8,%9}, {%0,%1,%2,%3};"
        : "+f"(d[0]), "+f"(d[1]), "+f"(d[2]), "+f"(d[3])
        : "r"(a[0]), "r"(a[1]), "r"(a[2]), "r"(a[3]), "r"(b0), "r"(b1));
}
__device__ __forceinline__ void ldsm4(uint32_t& r0, uint32_t& r1, uint32_t& r2, uint32_t& r3,
                                      uint32_t addr) {
    asm volatile("ldmatrix.sync.aligned.m8n8.x4.shared.b16 {%0,%1,%2,%3}, [%4];"
                 : "=r"(r0), "=r"(r1), "=r"(r2), "=r"(r3) : "r"(addr));
}

// 64B-pitch conflict-free tile swizzle (verified R10/R11)
__device__ __forceinline__ uint32_t swz(uint32_t r, uint32_t q) {
    return (r >> 1) * 128 + (((r & 1) * 4 + (q ^ ((r >> 1) & 3))) << 4);
}

__device__ __forceinline__ uint2 split4(float4 v) {
    __nv_bfloat16 hx = __float2bfloat16(v.x), hy = __float2bfloat16(v.y);
    __nv_bfloat16 hz = __float2bfloat16(v.z), hw = __float2bfloat16(v.w);
    __nv_bfloat162 p0 = __halves2bfloat162(hx, hy);
    __nv_bfloat162 p1 = __halves2bfloat162(hz, hw);
    return make_uint2(*(uint32_t*)&p0, *(uint32_t*)&p1);
}
__device__ __forceinline__ uint2 split4lo(float4 v, uint2 hi) {
    __nv_bfloat162 h0 = *(__nv_bfloat162*)&hi.x;
    __nv_bfloat162 h1 = *(__nv_bfloat162*)&hi.y;
    __nv_bfloat16 lx = __float2bfloat16(v.x - __bfloat162float(__low2bfloat16(h0)));
    __nv_bfloat16 ly = __float2bfloat16(v.y - __bfloat162float(__high2bfloat16(h0)));
    __nv_bfloat16 lz = __float2bfloat16(v.z - __bfloat162float(__low2bfloat16(h1)));
    __nv_bfloat16 lw = __float2bfloat16(v.w - __bfloat162float(__high2bfloat16(h1)));
    __nv_bfloat162 p0 = __halves2bfloat162(lx, ly);
    __nv_bfloat162 p1 = __halves2bfloat162(lz, lw);
    return make_uint2(*(uint32_t*)&p0, *(uint32_t*)&p1);
}

// ---------------- small utility kernels ----------------
__global__ __launch_bounds__(256) void zero_int_k(int* p, int n) {
    int i = blockIdx.x * 256 + threadIdx.x;
    if (i < n) p[i] = 0;
}
__global__ __launch_bounds__(256) void hist_k(const int* __restrict__ dst, int ne, int* deg) {
    int i = blockIdx.x * 256 + threadIdx.x;
    if (i < ne) atomicAdd(&deg[dst[i]], 1);
}
// hierarchical scan: per-block sums -> tiny scan -> expand (contention-robust)
__global__ __launch_bounds__(256) void blocksum_k(const int* __restrict__ deg,
                                                  int* __restrict__ bsum, int n) {
    __shared__ int sh[256];
    int t = threadIdx.x;
    int i = blockIdx.x * 256 + t;
    sh[t] = (i < n) ? deg[i] : 0;
    __syncthreads();
    for (int s = 128; s > 0; s >>= 1) {
        if (t < s) sh[t] += sh[t + s];
        __syncthreads();
    }
    if (t == 0) bsum[blockIdx.x] = sh[0];
}
__global__ void scanb_k(int* __restrict__ bsum, int nb) {
    __shared__ int sh[256];
    int t = threadIdx.x;
    int v = (t < nb) ? bsum[t] : 0;
    sh[t] = v;
    __syncthreads();
    for (int off = 1; off < 256; off <<= 1) {
        int u = (t >= off) ? sh[t - off] : 0;
        __syncthreads();
        sh[t] += u;
        __syncthreads();
    }
    if (t < nb) bsum[t] = sh[t] - v;   // exclusive prefix of block sums
}
__global__ __launch_bounds__(256) void expand_k(const int* __restrict__ deg,
                                                const int* __restrict__ bsumx,
                                                int* __restrict__ rowptr,
                                                int* __restrict__ cursor, int n) {
    __shared__ int sh[256];
    int t = threadIdx.x;
    int i = blockIdx.x * 256 + t;
    int v = (i < n) ? deg[i] : 0;
    sh[t] = v;
    __syncthreads();
    for (int off = 1; off < 256; off <<= 1) {
        int u = (t >= off) ? sh[t - off] : 0;
        __syncthreads();
        sh[t] += u;
        __syncthreads();
    }
    if (i < n) {
        int incl = sh[t] + bsumx[blockIdx.x];
        cursor[i] = incl - v;
        rowptr[i + 1] = incl;
    }
    if (i == 0) rowptr[0] = 0;
}
__global__ __launch_bounds__(256) void fill_k(const int* __restrict__ src, const int* __restrict__ dst,
                                              int ne, int* cursor, int* __restrict__ eidx) {
    int i = blockIdx.x * 256 + threadIdx.x;
    if (i < ne) {
        int p = atomicAdd(&cursor[dst[i]], 1);
        eidx[p] = src[i];
    }
}
__global__ void bounds_k(const int* __restrict__ gid, int n, int* __restrict__ gs) {
    int g = threadIdx.x;
    if (g > GNUM) return;
    int lo = 0, hi = n;
    while (lo < hi) {
        int mid = (lo + hi) >> 1;
        if (gid[mid] < g) lo = mid + 1; else hi = mid;
    }
    gs[g] = lo;
}

#define WSPLIT_TOT 557056
__global__ __launch_bounds__(256) void wsplit_all_k(const float* __restrict__ W_emb,
                                                    const float* __restrict__ W1,
                                                    const float* __restrict__ W2,
                                                    __nv_bfloat16* __restrict__ Wh,
                                                    __nv_bfloat16* __restrict__ Wl) {
    int i = blockIdx.x * 256 + threadIdx.x;
    if (i >= WSPLIT_TOT) return;
    const float* W;
    int idx, K;
    size_t base;
    if (i < 32768) {
        W = W_emb; idx = i; K = 128; base = W_EMB_OFF;
    } else if (i < 32768 + 262144) {
        int j = i - 32768;
        int l = j >> 16;
        W = W1 + (size_t)l * 65536; idx = j & 65535; K = 256; base = W1_OFF(l);
    } else {
        int j = i - 32768 - 262144;
        int l = j >> 16;
        W = W2 + (size_t)l * 65536; idx = j & 65535; K = 256; base = W2_OFF(l);
    }
    int k = idx >> 8, n = idx & 255;
    float x = W[idx];
    __nv_bfloat16 h = __float2bfloat16(x);
    float r = x - __bfloat162float(h);
    Wh[base + (size_t)n * K + k] = h;
    Wl[base + (size_t)n * K + k] = __float2bfloat16(r);
}

// ---------------- activation split (FOLD=1: relu(a*x+c) first) ----------------
template <int FOLD>
__global__ __launch_bounds__(256) void split_k(const float* __restrict__ T,
                                               const float* __restrict__ ac,
                                               __nv_bfloat16* __restrict__ Ah,
                                               __nv_bfloat16* __restrict__ Al, int n4) {
    int i = blockIdx.x * 256 + threadIdx.x;
    if (i >= n4) return;
    float4 v = ((const float4*)T)[i];
    if (FOLD) {
        int cb = (i * 4) & 255;
        float4 a = *(const float4*)&ac[cb];
        float4 c = *(const float4*)&ac[256 + cb];
        v.x = fmaxf(fmaf(a.x, v.x, c.x), 0.f);
        v.y = fmaxf(fmaf(a.y, v.y, c.y), 0.f);
        v.z = fmaxf(fmaf(a.z, v.z, c.z), 0.f);
        v.w = fmaxf(fmaf(a.w, v.w, c.w), 0.f);
    }
    uint2 hi = split4(v);
    uint2 lo = split4lo(v, hi);
    *(uint2*)(Ah + (size_t)i * 4) = hi;
    *(uint2*)(Al + (size_t)i * 4) = lo;
}

// ---------------- GIN aggregation (4-edge unrolled) -> split bf16 output ----------------
__global__ void agg_k(const float* __restrict__ H,
                      __nv_bfloat16* __restrict__ Ah, __nv_bfloat16* __restrict__ Al,
                      const int* __restrict__ rowptr, const int* __restrict__ eidx,
                      const float* __restrict__ eps, int l, int n) {
    int node = blockIdx.x * 8 + threadIdx.y;
    if (node >= n) return;
    int lane = threadIdx.x;
    const float4* h4 = (const float4*)(H + (size_t)node * DH);
    float ep = 1.0f + eps[l];
    float4 a0 = h4[lane];
    float4 a1 = h4[lane + 32];
    a0.x *= ep; a0.y *= ep; a0.z *= ep; a0.w *= ep;
    a1.x *= ep; a1.y *= ep; a1.z *= ep; a1.w *= ep;
    int beg = rowptr[node], end = rowptr[node + 1];
    int j = beg;
    for (; j + 3 < end; j += 4) {
        const float4* s0 = (const float4*)(H + (size_t)eidx[j] * DH);
        const float4* s1 = (const float4*)(H + (size_t)eidx[j + 1] * DH);
        const float4* s2 = (const float4*)(H + (size_t)eidx[j + 2] * DH);
        const float4* s3 = (const float4*)(H + (size_t)eidx[j + 3] * DH);
        float4 p00 = s0[lane], p01 = s0[lane + 32];
        float4 p10 = s1[lane], p11 = s1[lane + 32];
        float4 p20 = s2[lane], p21 = s2[lane + 32];
        float4 p30 = s3[lane], p31 = s3[lane + 32];
        a0.x += (p00.x + p10.x) + (p20.x + p30.x);
        a0.y += (p00.y + p10.y) + (p20.y + p30.y);
        a0.z += (p00.z + p10.z) + (p20.z + p30.z);
        a0.w += (p00.w + p10.w) + (p20.w + p30.w);
        a1.x += (p01.x + p11.x) + (p21.x + p31.x);
        a1.y += (p01.y + p11.y) + (p21.y + p31.y);
        a1.z += (p01.z + p11.z) + (p21.z + p31.z);
        a1.w += (p01.w + p11.w) + (p21.w + p31.w);
    }
    for (; j < end; j++) {
        const float4* sA = (const float4*)(H + (size_t)eidx[j] * DH);
        float4 pa0 = sA[lane], pa1 = sA[lane + 32];
        a0.x += pa0.x; a0.y += pa0.y; a0.z += pa0.z; a0.w += pa0.w;
        a1.x += pa1.x; a1.y += pa1.y; a1.z += pa1.z; a1.w += pa1.w;
    }
    uint2 h0 = split4(a0), h1 = split4(a1);
    uint2 l0 = split4lo(a0, h0), l1 = split4lo(a1, h1);
    size_t base = (size_t)node * DH + lane * 4;
    *(uint2*)(Ah + base) = h0;
    *(uint2*)(Ah + base + 128) = h1;
    *(uint2*)(Al + base) = l0;
    *(uint2*)(Al + base + 128) = l1;
}

// ---------------- all-bf16 mma.sync GEMM: 3-stage pipeline, merged hi/lo buffers ----------------
#define TSZ 8192
#define STG 32768
#define OFF_BIAS 98304
#define SMEM_GEMM (OFF_BIAS + 512)

__global__ __launch_bounds__(256, 2) void gemm_bf16_k(
    const __nv_bfloat16* __restrict__ A, uint32_t aLoB,
    const __nv_bfloat16* __restrict__ B, uint32_t bLoB,
    const float* __restrict__ bias, float* __restrict__ C, int M, int K)
{
    extern __shared__ char smem[];
    uint32_t sb = smem_u32(smem);
    int tid = threadIdx.x;
    int wid = tid >> 5, lane = tid & 31;
    int wm = wid >> 1, wn = wid & 1;
    int g = lane >> 2, tq = lane & 3;
    int m0 = blockIdx.x * 128, n0 = blockIdx.y * 128;
    int NC = K >> 5;

    if (tid < 32) ((float4*)(smem + OFF_BIAS))[tid] = ((const float4*)(bias + n0))[tid];

    int r1 = tid >> 2, q1 = tid & 3;
    uint32_t sw1 = swz((uint32_t)r1, (uint32_t)q1);
    int ar0 = min(m0 + r1, M - 1);
    int ar1 = min(m0 + r1 + 64, M - 1);
    const char* ag0 = (const char*)(A + (size_t)ar0 * K);
    const char* ag1 = (const char*)(A + (size_t)ar1 * K);
    const char* bg0 = (const char*)(B + (size_t)(n0 + r1) * K);
    const char* bg1 = (const char*)(B + (size_t)(n0 + r1 + 64) * K);

    auto issue = [&](int kc) {
        uint32_t bs = sb + (uint32_t)(kc % 3) * STG;
        int go = kc * 64 + q1 * 16;
        cp16(bs + sw1,                  ag0 + go);
        cp16(bs + sw1 + 4096,           ag1 + go);
        cp16(bs + TSZ + sw1,            ag0 + go + aLoB);
        cp16(bs + TSZ + sw1 + 4096,     ag1 + go + aLoB);
        cp16(bs + 2 * TSZ + sw1,        bg0 + go);
        cp16(bs + 2 * TSZ + sw1 + 4096, bg1 + go);
        cp16(bs + 3 * TSZ + sw1,        bg0 + go + bLoB);
        cp16(bs + 3 * TSZ + sw1 + 4096, bg1 + go + bLoB);
        CP_COMMIT();
    };

    uint32_t rA = (uint32_t)(wm * 32 + (lane & 15));
    uint32_t qA = (uint32_t)((lane >> 4) & 1);
    uint32_t aA0 = swz(rA, qA);
    uint32_t aA1 = swz(rA, qA + 2);
    uint32_t rB = (uint32_t)(wn * 64 + (lane & 7) + ((lane >> 4) & 1) * 8);
    uint32_t qB = (uint32_t)((lane >> 3) & 1);
    uint32_t bA0 = swz(rB, qB);
    uint32_t bA1 = swz(rB, qB + 2);

    float acc[2][8][4];
#pragma unroll
    for (int mt = 0; mt < 2; mt++)
#pragma unroll
        for (int nn = 0; nn < 8; nn++)
#pragma unroll
            for (int r = 0; r < 4; r++) acc[mt][nn][r] = 0.0f;

    issue(0);
    issue(1);

    for (int kc = 0; kc < NC; kc++) {
        if (kc + 1 < NC) { CP_WAIT1(); } else { CP_WAIT0(); }
        __syncthreads();
        if (kc + 2 < NC) issue(kc + 2);

        uint32_t st = sb + (uint32_t)(kc % 3) * STG;
#pragma unroll
        for (int ks = 0; ks < 2; ks++) {
            uint32_t aoff = st + (ks ? aA1 : aA0);
            uint32_t boff = st + 2 * TSZ + (ks ? bA1 : bA0);
            uint32_t ah[2][4], al[2][4];
#pragma unroll
            for (int mt = 0; mt < 2; mt++) {
                ldsm4(ah[mt][0], ah[mt][1], ah[mt][2], ah[mt][3], aoff + mt * 1024);
                ldsm4(al[mt][0], al[mt][1], al[mt][2], al[mt][3], aoff + TSZ + mt * 1024);
            }
#pragma unroll
            for (int np = 0; np < 4; np++) {
                uint32_t bb = boff + np * 1024;
                uint32_t bh0, bh1, bh2, bh3, bl0, bl1, bl2, bl3;
                ldsm4(bh0, bh1, bh2, bh3, bb);
                ldsm4(bl0, bl1, bl2, bl3, bb + TSZ);
                int nn = np * 2;
                mma16816(acc[0][nn],     ah[0], bh0, bh1);
                mma16816(acc[1][nn],     ah[1], bh0, bh1);
                mma16816(acc[0][nn + 1], ah[0], bh2, bh3);
                mma16816(acc[1][nn + 1], ah[1], bh2, bh3);
                mma16816(acc[0][nn],     ah[0], bl0, bl1);
                mma16816(acc[1][nn],     ah[1], bl0, bl1);
                mma16816(acc[0][nn + 1], ah[0], bl2, bl3);
                mma16816(acc[1][nn + 1], ah[1], bl2, bl3);
                mma16816(acc[0][nn],     al[0], bh0, bh1);
                mma16816(acc[1][nn],     al[1], bh0, bh1);
                mma16816(acc[0][nn + 1], al[0], bh2, bh3);
                mma16816(acc[1][nn + 1], al[1], bh2, bh3);
            }
        }
    }

    const float* biasS = (const float*)(smem + OFF_BIAS);
#pragma unroll
    for (int mt = 0; mt < 2; mt++) {
        int row = m0 + wm * 32 + mt * 16 + g;
#pragma unroll
        for (int nn = 0; nn < 8; nn++) {
            int colr = wn * 64 + nn * 8 + 2 * tq;
            float b0 = biasS[colr], b1 = biasS[colr + 1];
            int col = n0 + colr;
            if (row < M)
                *(float2*)&C[(size_t)row * 256 + col] =
                    make_float2(acc[mt][nn][0] + b0, acc[mt][nn][1] + b1);
            if (row + 8 < M)
                *(float2*)&C[(size_t)(row + 8) * 256 + col] =
                    make_float2(acc[mt][nn][2] + b0, acc[mt][nn][3] + b1);
        }
    }
}

// ---------------- column stats (4 independent row streams) ----------------
template <int TRANS>
__global__ void colstats_k(const float* __restrict__ T, const float* __restrict__ tac,
                           float* __restrict__ part, int M) {
    int c = threadIdx.x;
    int r0 = blockIdx.x * 256;
    float a = 0.f, b = 0.f;
    if (TRANS) { a = tac[c]; b = tac[256 + c]; }
    float s0 = 0.f, s1 = 0.f, s2 = 0.f, s3 = 0.f;
    float q0 = 0.f, q1 = 0.f, q2 = 0.f, q3 = 0.f;
    const float* base = T + c;
#pragma unroll 4
    for (int j = 0; j < 64; j++) {
        int r = r0 + j;
        float x0 = (r < M)       ? base[(size_t)r * DH]         : 0.f;
        float x1 = (r + 64 < M)  ? base[(size_t)(r + 64) * DH]  : 0.f;
        float x2 = (r + 128 < M) ? base[(size_t)(r + 128) * DH] : 0.f;
        float x3 = (r + 192 < M) ? base[(size_t)(r + 192) * DH] : 0.f;
        if (TRANS) {
            x0 = (r < M)       ? fmaxf(fmaf(a, x0, b), 0.f) : 0.f;
            x1 = (r + 64 < M)  ? fmaxf(fmaf(a, x1, b), 0.f) : 0.f;
            x2 = (r + 128 < M) ? fmaxf(fmaf(a, x2, b), 0.f) : 0.f;
            x3 = (r + 192 < M) ? fmaxf(fmaf(a, x3, b), 0.f) : 0.f;
        }
        s0 += x0; q0 += x0 * x0;
        s1 += x1; q1 += x1 * x1;
        s2 += x2; q2 += x2 * x2;
        s3 += x3; q3 += x3 * x3;
    }
    part[blockIdx.x * 512 + c] = (s0 + s1) + (s2 + s3);
    part[blockIdx.x * 512 + 256 + c] = (q0 + q1) + (q2 + q3);
}

__global__ void finalize_k(const float* __restrict__ part, int nb, int n,
                           const float* __restrict__ gamma, const float* __restrict__ beta,
                           float* __restrict__ ac) {
    __shared__ float sh[4][512];
    int c = threadIdx.x & 255;
    int seg = threadIdx.x >> 8;
    int b0 = (nb * seg) >> 2, b1 = (nb * (seg + 1)) >> 2;
    float s = 0.f, ss = 0.f;
    for (int b = b0; b < b1; b++) {
        s += part[b * 512 + c];
        ss += part[b * 512 + 256 + c];
    }
    sh[seg][c] = s;
    sh[seg][256 + c] = ss;
    __syncthreads();
    if (seg == 0) {
        float ts = (sh[0][c] + sh[1][c]) + (sh[2][c] + sh[3][c]);
        float tss = (sh[0][256 + c] + sh[1][256 + c]) + (sh[2][256 + c] + sh[3][256 + c]);
        float inv = 1.0f / (float)n;
        float m = ts * inv;
        float v = tss * inv - m * m;
        float a = gamma[c] * rsqrtf(v + BN_EPS);
        ac[c] = a;
        ac[256 + c] = beta[c] - a * m;
    }
}

__global__ __launch_bounds__(256) void update_k(float* __restrict__ H, const float* __restrict__ T2,
                                                const float* __restrict__ acA, const float* __restrict__ acG,
                                                int n4) {
    int i = blockIdx.x * 256 + threadIdx.x;
    if (i >= n4) return;
    int cb = (i * 4) & 255;
    float4 t  = ((const float4*)T2)[i];
    float4 aA = *(const float4*)&acA[cb];
    float4 cA = *(const float4*)&acA[256 + cb];
    float4 aG = *(const float4*)&acG[cb];
    float4 cG = *(const float4*)&acG[256 + cb];
    float4 h  = ((float4*)H)[i];
    h.x += fmaxf(aG.x * fmaxf(aA.x * t.x + cA.x, 0.f) + cG.x, 0.f);
    h.y += fmaxf(aG.y * fmaxf(aA.y * t.y + cA.y, 0.f) + cG.y, 0.f);
    h.z += fmaxf(aG.z * fmaxf(aA.z * t.z + cA.z, 0.f) + cG.z, 0.f);
    h.w += fmaxf(aG.w * fmaxf(aA.w * t.w + cA.w, 0.f) + cG.w, 0.f);
    ((float4*)H)[i] = h;
}

// ---------------- two-phase readout (contention-robust, deterministic) ----------------
__global__ void readout1_k(const float* __restrict__ H, const int* __restrict__ gs,
                           float* __restrict__ part) {
    int g = blockIdx.x, seg = blockIdx.y;   // 8 segments per group
    int c = threadIdx.x;
    int beg = gs[g], end = gs[g + 1];
    int len = end - beg;
    int b0 = beg + (int)(((long long)len * seg) >> 3);
    int b1 = beg + (int)(((long long)len * (seg + 1)) >> 3);
    float s = 0.f;
    for (int i = b0; i < b1; i++) s += H[(size_t)i * DH + c];
    part[((size_t)g * 8 + seg) * 256 + c] = s;
}
__global__ void readout2_k(const float* __restrict__ part, float* __restrict__ R) {
    int g = blockIdx.x;
    int c = threadIdx.x;
    float s = 0.f;
#pragma unroll
    for (int k = 0; k < 8; k++) s += part[((size_t)g * 8 + k) * 256 + c];
    R[g * DH + c] = s;
}

__global__ void predict_k(const float* __restrict__ Rg, const float* __restrict__ Rq,
                          const float* __restrict__ Wp1, const float* __restrict__ bp1,
                          const float* __restrict__ Wp2, const float* __restrict__ bp2,
                          float* __restrict__ out) {
    int g = blockIdx.x;
    int t = threadIdx.x;
    __shared__ float d[256];
    __shared__ float red[256];
    d[t] = fabsf(Rg[g * DH + t] - Rq[g * DH + t]);
    __syncthreads();
    float acc = bp1[t];
    for (int k = 0; k < 256; k++) acc += d[k] * Wp1[k * 256 + t];
    acc = fmaxf(acc, 0.f);
    red[t] = acc * Wp2[t];
    __syncthreads();
    for (int s = 128; s > 0; s >>= 1) {
        if (t < s) red[t] += red[t + s];
        __syncthreads();
    }
    if (t == 0) out[g] = red[0] + bp2[0];
}

// ---------------- host orchestration ----------------
struct Scratch {
    float *H, *T1, *T2, *part, *ac;
    __nv_bfloat16 *Ah, *Al;
    uint32_t aLoB;
    int *deg, *rowptr, *cursor, *eidx, *bsum, *gstart;
};

static void build_csr(cudaStream_t st, const Scratch& sc, int n,
                      const int* src, const int* dst, int ne, const int* gid) {
    int nb = (n + 255) / 256;
    zero_int_k<<<(n + 256) / 256, 256, 0, st>>>(sc.deg, n + 1);
    hist_k<<<(ne + 255) / 256, 256, 0, st>>>(dst, ne, sc.deg);
    blocksum_k<<<nb, 256, 0, st>>>(sc.deg, sc.bsum, n);
    scanb_k<<<1, 256, 0, st>>>(sc.bsum, nb);
    expand_k<<<nb, 256, 0, st>>>(sc.deg, sc.bsum, sc.rowptr, sc.cursor, n);
    fill_k<<<(ne + 255) / 256, 256, 0, st>>>(src, dst, ne, sc.cursor, sc.eidx);
    bounds_k<<<1, GNUM + 1, 0, st>>>(gid, n, sc.gstart);
}

static void run_layers(cudaStream_t st, const Scratch& sc, const __nv_bfloat16* Wbase,
                       int n, const float* eps,
                       const float* b1, const float* bn1_g, const float* bn1_b,
                       const float* b2, const float* bnA_g, const float* bnA_b,
                       const float* bnG_g, const float* bnG_b,
                       float* R) {
    int gx = (n + 127) / 128;
    dim3 gg(gx, 2);
    int sb = (n + 255) / 256;
    for (int l = 0; l < 4; l++) {
        int bo = l * 256;
        agg_k<<<(n + 7) / 8, dim3(32, 8), 0, st>>>(sc.H, sc.Ah, sc.Al, sc.rowptr, sc.eidx, eps, l, n);
        gemm_bf16_k<<<gg, 256, SMEM_GEMM, st>>>(sc.Ah, sc.aLoB, Wbase + W1_OFF(l), W_LO_B,
                                                b1 + bo, sc.T1, n, 256);
        colstats_k<0><<<sb, 256, 0, st>>>(sc.T1, nullptr, sc.part, n);
        finalize_k<<<1, 1024, 0, st>>>(sc.part, sb, n, bn1_g + bo, bn1_b + bo, sc.ac);
        split_k<1><<<(n * 64 + 255) / 256, 256, 0, st>>>(sc.T1, sc.ac, sc.Ah, sc.Al, n * 64);
        gemm_bf16_k<<<gg, 256, SMEM_GEMM, st>>>(sc.Ah, sc.aLoB, Wbase + W2_OFF(l), W_LO_B,
                                                b2 + bo, sc.T2, n, 256);
        colstats_k<0><<<sb, 256, 0, st>>>(sc.T2, nullptr, sc.part, n);
        finalize_k<<<1, 1024, 0, st>>>(sc.part, sb, n, bnA_g + bo, bnA_b + bo, sc.ac + 512);
        colstats_k<1><<<sb, 256, 0, st>>>(sc.T2, sc.ac + 512, sc.part, n);
        finalize_k<<<1, 1024, 0, st>>>(sc.part, sb, n, bnG_g + bo, bnG_b + bo, sc.ac + 1024);
        update_k<<<((n * 64) + 255) / 256, 256, 0, st>>>(sc.H, sc.T2, sc.ac + 512, sc.ac + 1024, n * 64);
    }
    readout1_k<<<dim3(GNUM, 8), 256, 0, st>>>(sc.H, sc.gstart, sc.part);
    readout2_k<<<GNUM, 256, 0, st>>>(sc.part, R);
}

extern "C" void kernel_launch(void* const* d_in, const int* in_sizes, int n_in,
                              void* d_out, int out_size) {
    const float* X     = (const float*)d_in[0];
    const float* X_q   = (const float*)d_in[2];
    const float* W_emb = (const float*)d_in[4];
    const float* b_emb = (const float*)d_in[5];
    const float* eps   = (const float*)d_in[6];
    const float* W1    = (const float*)d_in[7];
    const float* b1    = (const float*)d_in[8];
    const float* bn1_g = (const float*)d_in[9];
    const float* bn1_b = (const float*)d_in[10];
    const float* W2    = (const float*)d_in[11];
    const float* b2    = (const float*)d_in[12];
    const float* bnA_g = (const float*)d_in[13];
    const float* bnA_b = (const float*)d_in[14];
    const float* bnG_g = (const float*)d_in[15];
    const float* bnG_b = (const float*)d_in[16];
    const float* Wp1   = (const float*)d_in[17];
    const float* bp1   = (const float*)d_in[18];
    const float* Wp2   = (const float*)d_in[19];
    const float* bp2   = (const float*)d_in[20];
    const int* src_g   = (const int*)d_in[21];
    const int* dst_g   = (const int*)d_in[22];
    const int* gid_g   = (const int*)d_in[23];
    const int* src_q   = (const int*)d_in[24];
    const int* dst_q   = (const int*)d_in[25];
    const int* gid_q   = (const int*)d_in[26];

    int n_g = in_sizes[0] / 128;
    int e_g = in_sizes[21];
    int n_q = in_sizes[2] / 128;
    int e_q = in_sizes[24];

    Scratch sg, sq;
    __nv_bfloat16 *A2g, *A2q, *Wbase;
    cudaGetSymbolAddress((void**)&sg.H, g_H);
    cudaGetSymbolAddress((void**)&sg.T1, g_T1);
    cudaGetSymbolAddress((void**)&sg.T2, g_T2);
    cudaGetSymbolAddress((void**)&sg.part, g_part);
    cudaGetSymbolAddress((void**)&sg.ac, g_ac);
    cudaGetSymbolAddress((void**)&A2g, g_A2);
    cudaGetSymbolAddress((void**)&sg.deg, g_deg);
    cudaGetSymbolAddress((void**)&sg.rowptr, g_rowptr);
    cudaGetSymbolAddress((void**)&sg.cursor, g_cursor);
    cudaGetSymbolAddress((void**)&sg.eidx, g_eidx);
    cudaGetSymbolAddress((void**)&sg.bsum, g_bsum);
    cudaGetSymbolAddress((void**)&sg.gstart, g_gstart);
    cudaGetSymbolAddress((void**)&sq.H, q_H);
    cudaGetSymbolAddress((void**)&sq.T1, q_T1);
    cudaGetSymbolAddress((void**)&sq.T2, q_T2);
    cudaGetSymbolAddress((void**)&sq.part, q_part);
    cudaGetSymbolAddress((void**)&sq.ac, q_ac);
    cudaGetSymbolAddress((void**)&A2q, q_A2);
    cudaGetSymbolAddress((void**)&sq.deg, q_deg);
    cudaGetSymbolAddress((void**)&sq.rowptr, q_rowptr);
    cudaGetSymbolAddress((void**)&sq.cursor, q_cursor);
    cudaGetSymbolAddress((void**)&sq.eidx, q_eidx);
    cudaGetSymbolAddress((void**)&sq.bsum, q_bsum);
    cudaGetSymbolAddress((void**)&sq.gstart, q_gstart);
    cudaGetSymbolAddress((void**)&Wbase, g_W2);
    float* R;
    cudaGetSymbolAddress((void**)&R, g_R);

    sg.Ah = A2g; sg.Al = A2g + (size_t)NMAX * DH; sg.aLoB = A_LO_B_G;
    sq.Ah = A2q; sq.Al = A2q + (size_t)NQMAX * DH; sq.aLoB = A_LO_B_Q;

    cudaFuncSetAttribute(gemm_bf16_k, cudaFuncAttributeMaxDynamicSharedMemorySize, SMEM_GEMM);

    // single extra stream (proven footprint)
    cudaStream_t s2;
    cudaEvent_t evFork, evJoin, evCsrG;
    cudaStreamCreateWithFlags(&s2, cudaStreamNonBlocking);
    cudaEventCreateWithFlags(&evFork, cudaEventDisableTiming);
    cudaEventCreateWithFlags(&evJoin, cudaEventDisableTiming);
    cudaEventCreateWithFlags(&evCsrG, cudaEventDisableTiming);

    wsplit_all_k<<<(WSPLIT_TOT + 255) / 256, 256>>>(W_emb, W1, W2,
                                                    Wbase, Wbase + WTOT);

    cudaEventRecord(evFork, 0);
    cudaStreamWaitEvent(s2, evFork, 0);

    // s2: g-CSR first (overlaps g-stream's split + emb GEMM), then q pipeline
    build_csr(s2, sg, n_g, src_g, dst_g, e_g, gid_g);
    cudaEventRecord(evCsrG, s2);

    // g-stream: split + emb GEMM, then wait for CSR-g, then layers
    split_k<0><<<(n_g * 32 + 255) / 256, 256>>>(X, nullptr, sg.Ah, sg.Al, n_g * 32);
    gemm_bf16_k<<<dim3((n_g + 127) / 128, 2), 256, SMEM_GEMM>>>(
        sg.Ah, sg.aLoB, Wbase + W_EMB_OFF, W_LO_B, b_emb, sg.H, n_g, 128);
    cudaStreamWaitEvent((cudaStream_t)0, evCsrG, 0);
    run_layers((cudaStream_t)0, sg, Wbase, n_g, eps,
               b1, bn1_g, bn1_b, b2, bnA_g, bnA_b, bnG_g, bnG_b, R);

    // s2: q pipeline (CSR inline on s2)
    build_csr(s2, sq, n_q, src_q, dst_q, e_q, gid_q);
    split_k<0><<<(n_q * 32 + 255) / 256, 256, 0, s2>>>(X_q, nullptr, sq.Ah, sq.Al, n_q * 32);
    gemm_bf16_k<<<dim3((n_q + 127) / 128, 2), 256, SMEM_GEMM, s2>>>(
        sq.Ah, sq.aLoB, Wbase + W_EMB_OFF, W_LO_B, b_emb, sq.H, n_q, 128);
    run_layers(s2, sq, Wbase, n_q, eps,
               b1, bn1_g, bn1_b, b2, bnA_g, bnA_b, bnG_g, bnG_b, R + GNUM * DH);

    cudaEventRecord(evJoin, s2);
    cudaStreamWaitEvent((cudaStream_t)0, evJoin, 0);

    predict_k<<<GNUM, 256>>>(R, R + GNUM * DH, Wp1, bp1, Wp2, bp2, (float*)d_out);
}